// round 12
// baseline (speedup 1.0000x reference)
#include <cuda_runtime.h>
#include <cuda_fp16.h>

typedef unsigned int u32;

#define TPB 256
#define EPC 256            // edges per CTA (8 warps x 32 rows)
#define FSTR 34            // fp32 feat scratch row stride (words)

#define SM_FF 0            // feat A-frags: 8w * 2ks * 2m * 512B = 16K
#define SM_EF 16384        // ef A-frags:   8w * 8ks * 2m * 512B = 64K (+scratch alias)
#define SM_HH 81920        // h  A-frags:   8w * 4ks * 2m * 512B = 32K
#define SM_TOTAL 114688

// ---- prepacked f16 weight image, uint4 = two n-adjacent B fragments ---------
#define PACK_TOT  27392
#define PACK4_TOT 13696
#define OFF4_WF      0
#define OFF4_W1(l)   (512   + (l) * 1152)
#define OFF4_W2(l)   (3968  + (l) * 512)
#define OFF4_W3(l)   (5504  + (l) * 1024)
#define OFF4_TP1(l)  (8576  + (l) * 256)
#define OFF4_TP2(l)  (9344  + (l) * 1024)
#define OFF4_HW1     12416
#define OFF4_HW2     13440

__device__ uint4  gW4[PACK4_TOT];
__device__ unsigned short gH[4 * PACK_TOT];   // canonical [seg][k][n] f16 image
__device__ double g_partial[8192];
__device__ float  gP0[100 * 128];
__device__ float  gP1[100 * 128];
__device__ float  gR [3 * 2 * 100 * 64];

__constant__ int c_soff[19] = {0, 1024, 3328, 5632, 7936, 8960, 9984,
                               11008, 13056, 15104, 17152, 17664, 18176,
                               18688, 20736, 22784, 24832, 26880, 27392};
__constant__ int c_soff4[19] = {0, 512, 1664, 2816, 3968, 4480, 4992,
                                5504, 6528, 7552, 8576, 8832, 9088,
                                9344, 10368, 11392, 12416, 13440, 13696};
__constant__ int c_ntg [18] = {16, 8,8,8, 8,8,8, 16,16,16, 8,8,8, 16,16,16, 8, 4};
__constant__ int c_n   [18] = {128, 64,64,64, 64,64,64, 128,128,128,
                               64,64,64, 128,128,128, 64, 32};
__constant__ int c_kreal[18]= {17, 136,136,136, 64,64,64, 64,64,64,
                               17,17,17, 64,64,64, 128, 64};
__constant__ int c_remap[18]= {0, 1,1,1, 0,0,0, 0,0,0, 2,2,2, 0,0,0, 0, 0};
__constant__ int c_src [18] = {0, 1,1,1, 2,2,2, 3,3,3, 4,4,4, 5,5,5, 6, 7};
__constant__ int c_woff[18] = {16384, 0,16896,33792, 0,4096,8192, 0,8192,16384,
                               0,576,1152, 0,8192,16384, 0, 0};
__constant__ int c_ncol[19] = {0, 128, 192, 256, 320, 384, 448, 512,
                               640, 768, 896, 960, 1024, 1088,
                               1216, 1344, 1472, 1536, 1568};

// ---------------- low-level helpers -----------------------------------------
__device__ __forceinline__ u32 smem_u32(const void* p){
    u32 a;
    asm("{ .reg .u64 t; cvta.to.shared.u64 t, %1; cvt.u32.u64 %0, t; }"
        : "=r"(a) : "l"(p));
    return a;
}
__device__ __forceinline__ float silu_f(float x){ return x / (1.0f + __expf(-x)); }
__device__ __forceinline__ void stsf(u32 a, float v){
    asm volatile("st.shared.f32 [%0], %1;" :: "r"(a), "f"(v));
}
__device__ __forceinline__ float2 ldsf2(u32 a){
    float2 v; asm volatile("ld.shared.v2.f32 {%0,%1}, [%2];"
                           : "=f"(v.x), "=f"(v.y) : "r"(a));
    return v;
}
__device__ __forceinline__ uint4 lds128(u32 a){
    uint4 v; asm volatile("ld.shared.v4.u32 {%0,%1,%2,%3}, [%4];"
        : "=r"(v.x), "=r"(v.y), "=r"(v.z), "=r"(v.w) : "r"(a));
    return v;
}
__device__ __forceinline__ uint2 lds64(u32 a){
    uint2 v; asm volatile("ld.shared.v2.u32 {%0,%1}, [%2];"
        : "=r"(v.x), "=r"(v.y) : "r"(a));
    return v;
}
__device__ __forceinline__ void sts64(u32 a, u32 x, u32 y){
    asm volatile("st.shared.v2.u32 [%0], {%1,%2};" :: "r"(a), "r"(x), "r"(y));
}
__device__ __forceinline__ void sts128(u32 a, u32 x, u32 y, u32 z, u32 w){
    asm volatile("st.shared.v4.u32 [%0], {%1,%2,%3,%4};"
                 :: "r"(a), "r"(x), "r"(y), "r"(z), "r"(w));
}
// pack two f32 -> f16x2 (first src lands in HIGH half)
__device__ __forceinline__ u32 f16x2(float hi, float lo){
    u32 r; asm("cvt.rn.f16x2.f32 %0, %1, %2;" : "=r"(r) : "f"(hi), "f"(lo));
    return r;
}
__device__ __forceinline__ float2 h2f(u32 v){
    float2 f;
    asm("{.reg .f16 l, h; mov.b32 {l, h}, %2; cvt.f32.f16 %0, l; cvt.f32.f16 %1, h;}"
        : "=f"(f.x), "=f"(f.y) : "r"(v));
    return f;
}
__device__ __forceinline__ void mma_f16(float* d, const u32* a, u32 b0, u32 b1){
    asm volatile("mma.sync.aligned.m16n8k16.row.col.f32.f16.f16.f32 "
        "{%0,%1,%2,%3}, {%4,%5,%6,%7}, {%8,%9}, {%0,%1,%2,%3};"
        : "+f"(d[0]), "+f"(d[1]), "+f"(d[2]), "+f"(d[3])
        : "r"(a[0]), "r"(a[1]), "r"(a[2]), "r"(a[3]), "r"(b0), "r"(b1));
}

template<int NT>
__device__ __forceinline__ void zeroN(float (*a)[4]){
#pragma unroll
    for (int i = 0; i < NT; i++)
#pragma unroll
        for (int j = 0; j < 4; j++) a[i][j] = 0.0f;
}

// ---- warp GEMM, M=32 (two m16 tiles share every B fragment) -----------------
// aAddr = slot base (incl. warp/lane/A-kstep offset); kstep group stride 1024B,
// m-tile stride 512B.
template<int NKS, int NTP>
__device__ __forceinline__ void gemmF2(float (*acc0)[4], float (*acc1)[4],
                                       u32 aAddr, const uint4* __restrict__ B,
                                       int NTGP, int ntgp0, int ksB0, int lane){
#pragma unroll
    for (int s = 0; s < NKS; s++){
        uint4 av0 = lds128(aAddr + (u32)(2 * s)     * 512u);
        uint4 av1 = lds128(aAddr + (u32)(2 * s + 1) * 512u);
        u32 a0[4] = {av0.x, av0.y, av0.z, av0.w};
        u32 a1[4] = {av1.x, av1.y, av1.z, av1.w};
        const uint4* bp = B + ((u32)(ksB0 + s) * NTGP + ntgp0) * 32 + lane;
#pragma unroll
        for (int p = 0; p < NTP; p++){
            uint4 b = __ldg(bp + p * 32);
            mma_f16(acc0[2 * p],     a0, b.x, b.y);
            mma_f16(acc0[2 * p + 1], a0, b.z, b.w);
            mma_f16(acc1[2 * p],     a1, b.x, b.y);
            mma_f16(acc1[2 * p + 1], a1, b.z, b.w);
        }
    }
}

// ---------------------------------------------------------------------------
// round_kernel: cascade (error-feedback) rounding of each weight column to f16.
__global__ void round_kernel(const float* __restrict__ w_init,
                             const float* __restrict__ w1,
                             const float* __restrict__ w2,
                             const float* __restrict__ w3,
                             const float* __restrict__ tpw1,
                             const float* __restrict__ tpw2,
                             const float* __restrict__ hw1,
                             const float* __restrict__ hw2)
{
    int col = blockIdx.x * blockDim.x + threadIdx.x;
    if (col >= 1568) return;
    int s = 0;
    while (s + 1 < 18 && col >= c_ncol[s + 1]) s++;
    int n = col - c_ncol[s];
    const float* srcs[8] = {w_init, w1, w2, w3, tpw1, tpw2, hw1, hw2};
    const float* W = srcs[c_src[s]] + c_woff[s];
    int N = c_n[s], Kreal = c_kreal[s], remap = c_remap[s];
    int Kpad = 16 * ((c_soff[s + 1] - c_soff[s]) / (c_ntg[s] * 32));
    unsigned short* out = gH + 4 * c_soff[s];
    float e = 0.0f;
    for (int k = 0; k < Kpad; k++){
        int r = k;
        bool real = true;
        if (remap == 1){
            if (k < 128)      r = k;
            else if (k < 136) r = k + 128;
            else              real = false;
        } else if (remap == 2){           // tpw1: shifted by +8 (sh at cols 8..16)
            if (k >= 8 && k < 17) r = k - 8; else real = false;
        } else {
            if (k >= Kreal) real = false;
        }
        unsigned short q = 0;
        if (real){
            float tt = __ldg(W + r * N + n) + e;
            __half h = __float2half_rn(tt);
            e = tt - __half2float(h);
            q = __half_as_ushort(h);
        }
        out[k * N + n] = q;
    }
}

// pack_frag: gather rounded f16 into uint4 image (two n-adjacent fragments).
__global__ void pack_frag_kernel()
{
    int i = blockIdx.x * blockDim.x + threadIdx.x;
    if (i >= PACK4_TOT) return;
    int s = 0;
    while (s + 1 < 18 && i >= c_soff4[s + 1]) s++;
    int local = i - c_soff4[s];
    int lane = local & 31, rest = local >> 5;
    int NTGP = c_ntg[s] >> 1;
    int ntgp = rest % NTGP, ks = rest / NTGP;
    int t = lane & 3, g = lane >> 2;
    int N = c_n[s];
    const unsigned short* src = gH + 4 * c_soff[s];
    int k0 = ks * 16 + 2 * t;
    int n0 = (2 * ntgp) * 8 + g;
    int n1 = n0 + 8;
    u32 a0 = src[(k0    ) * N + n0], a1 = src[(k0 + 1) * N + n0];
    u32 a8 = src[(k0 + 8) * N + n0], a9 = src[(k0 + 9) * N + n0];
    u32 b0 = src[(k0    ) * N + n1], b1 = src[(k0 + 1) * N + n1];
    u32 b8 = src[(k0 + 8) * N + n1], b9 = src[(k0 + 9) * N + n1];
    uint4 o;
    o.x = a0 | (a1 << 16);
    o.y = a8 | (a9 << 16);
    o.z = b0 | (b1 << 16);
    o.w = b8 | (b9 << 16);
    gW4[i] = o;
}

// ---------------------------------------------------------------------------
__global__ __launch_bounds__(TPB, 2) void edge_kernel(
    const int *__restrict__ an, const float *__restrict__ pos,
    const int *__restrict__ eidx,
    const float *__restrict__ b_init,
    const float *__restrict__ b1, const float *__restrict__ b2,
    const float *__restrict__ b3,
    const float *__restrict__ ln_g, const float *__restrict__ ln_b,
    const float *__restrict__ tpb1, const float *__restrict__ tpb2,
    const float *__restrict__ hb1, const float *__restrict__ hb2,
    const float *__restrict__ hw3,
    int E)
{
    extern __shared__ char smem[];
    const u32 sb  = smem_u32(smem);
    const int tid = threadIdx.x;
    const int warp = tid >> 5, lane = tid & 31;
    const int g = lane >> 2, t = lane & 3;

    // ---------------- own edge: features into fp32 scratch (EF alias) --------
    int e = blockIdx.x * EPC + tid;
    if (e >= E) e = E - 1;
    int myTi, myTj;
    {
        const int rowi = eidx[e];
        const int coli = eidx[E + e];
        myTi = an[rowi];
        myTj = an[coli];
        const float vx = pos[3 * coli + 0] - pos[3 * rowi + 0];
        const float vy = pos[3 * coli + 1] - pos[3 * rowi + 1];
        const float vz = pos[3 * coli + 2] - pos[3 * rowi + 2];
        const float d = sqrtf(vx * vx + vy * vy + vz * vz);

        u32 r0 = sb + SM_EF + (u32)tid * (FSTR * 4);
        float env = (d < 5.0f) ? (0.5f * (cosf(d * 0.6283185307179586f) + 1.0f)) : 0.0f;
        const float cen[8] = { 0.98078528040323044f,  0.83146961230254524f,
                               0.55557023301960218f,  0.19509032201612825f,
                              -0.19509032201612825f, -0.55557023301960218f,
                              -0.83146961230254524f, -0.98078528040323044f};
#pragma unroll
        for (int i = 0; i < 8; i++){
            float z = (d - cen[i] * 5.0f) * 1.6f;
            stsf(r0 + i * 4, __expf(-0.5f * z * z) * env);
        }
        float r = fmaxf(d, 1e-8f);
        float inv = 1.0f / r;
        float ux = vx * inv, uy = vy * inv, uz = vz * inv;
        stsf(r0 +  8 * 4, 0.28209479177387814f);
        stsf(r0 +  9 * 4, -0.4886025119029199f * uy);
        stsf(r0 + 10 * 4,  0.4886025119029199f * uz);
        stsf(r0 + 11 * 4, -0.4886025119029199f * ux);
        stsf(r0 + 12 * 4,  1.0925484305920792f * ux * uy);
        stsf(r0 + 13 * 4, -1.0925484305920792f * uy * uz);
        stsf(r0 + 14 * 4,  0.94617469575756f * uz * uz
                          - 0.31539156525252f * (ux * ux + uy * uy));
        stsf(r0 + 15 * 4, -1.0925484305920792f * ux * uz);
        stsf(r0 + 16 * 4,  0.5462742152960396f * (ux * ux - uy * uy));
#pragma unroll
        for (int i = 17; i < 32; i++) stsf(r0 + i * 4, 0.0f);
    }
    __syncwarp();

    // atom types for this thread's 4 rows (row owner lane = local row index)
    int tiR[4], tjR[4];
#pragma unroll
    for (int k = 0; k < 4; k++){
        int src = g + 8 * k;
        tiR[k] = __shfl_sync(0xffffffffu, myTi, src);
        tjR[k] = __shfl_sync(0xffffffffu, myTj, src);
    }

    // pack featF A-fragments (warp-local; scratch rows owned by same warp)
    {
        u32 scr = sb + SM_EF;
        u32 ffW = sb + SM_FF + (u32)warp * 2048u;
#pragma unroll
        for (int ks = 0; ks < 2; ks++)
#pragma unroll
        for (int m = 0; m < 2; m++){
            int r0 = warp * 32 + m * 16 + g;
            u32 base = scr + ((u32)r0 * FSTR + (u32)(ks * 16 + 2 * t)) * 4u;
            float2 q0 = ldsf2(base);
            float2 q1 = ldsf2(base + 8u * FSTR * 4u);
            float2 q2 = ldsf2(base + 32u);
            float2 q3 = ldsf2(base + 8u * FSTR * 4u + 32u);
            sts128(ffW + (u32)(ks * 2 + m) * 512u + (u32)lane * 16u,
                   f16x2(q0.y, q0.x), f16x2(q1.y, q1.x),
                   f16x2(q2.y, q2.x), f16x2(q3.y, q3.x));
        }
    }
    __syncthreads();   // scratch dead everywhere before EF-frag writes

    const u32 aFF = sb + SM_FF + (u32)warp * 2048u + (u32)lane * 16u;
    const u32 aEF = sb + SM_EF + (u32)warp * 8192u + (u32)lane * 16u;
    const u32 aHH = sb + SM_HH + (u32)warp * 4096u + (u32)lane * 16u;

    float acc0[8][4], acc1[8][4];

    // ========== G0: ef = feat @ Wf + P0[ai] + P1[aj] + b_init ================
#pragma unroll
    for (int p = 0; p < 2; p++){
        zeroN<8>(acc0); zeroN<8>(acc1);
        gemmF2<2, 4>(acc0, acc1, aFF, gW4 + OFF4_WF, 8, p * 4, 0, lane);
#pragma unroll
        for (int nt = 0; nt < 8; nt++){
            int c = p * 64 + nt * 8 + 2 * t;
            float2 bb = *(const float2*)(b_init + c);
            float v[8];
#pragma unroll
            for (int k = 0; k < 4; k++){
                float2 q0 = *(const float2*)(gP0 + tiR[k] * 128 + c);
                float2 q1 = *(const float2*)(gP1 + tjR[k] * 128 + c);
                const float* A = (k < 2) ? acc0[nt] : acc1[nt];
                v[2 * k]     = A[(k & 1) * 2]     + bb.x + q0.x + q1.x;
                v[2 * k + 1] = A[(k & 1) * 2 + 1] + bb.y + q0.y + q1.y;
            }
            int idx = p * 8 + nt;
            u32 a0 = aEF + (u32)(idx >> 1) * 1024u + (u32)(idx & 1) * 8u;
            sts64(a0,        f16x2(v[1], v[0]), f16x2(v[3], v[2]));
            sts64(a0 + 512u, f16x2(v[5], v[4]), f16x2(v[7], v[6]));
        }
    }

    float mu[4], rs[4];

    // ========== layers =======================================================
#pragma unroll 1
    for (int l = 0; l < 3; l++){
        // --- G1: h = silu(ef@W1a + rbf@W1b + R0[ai] + R1[aj] + b1) ---
        {
            const uint4* B = gW4 + OFF4_W1(l);
            zeroN<8>(acc0); zeroN<8>(acc1);
            gemmF2<8, 4>(acc0, acc1, aEF, B, 4, 0, 0, lane);
            gemmF2<1, 4>(acc0, acc1, aFF, B, 4, 0, 8, lane);  // rbf tail
            const float* B1 = b1 + l * 64;
            const float* R0b = gR + (l * 2    ) * 6400;
            const float* R1b = gR + (l * 2 + 1) * 6400;
#pragma unroll
            for (int nt = 0; nt < 8; nt++){
                int c = nt * 8 + 2 * t;
                float2 bb = *(const float2*)(B1 + c);
                float v[8];
#pragma unroll
                for (int k = 0; k < 4; k++){
                    float2 x0 = *(const float2*)(R0b + tiR[k] * 64 + c);
                    float2 x1 = *(const float2*)(R1b + tjR[k] * 64 + c);
                    const float* A = (k < 2) ? acc0[nt] : acc1[nt];
                    v[2 * k]     = silu_f(A[(k & 1) * 2]     + bb.x + x0.x + x1.x);
                    v[2 * k + 1] = silu_f(A[(k & 1) * 2 + 1] + bb.y + x0.y + x1.y);
                }
                u32 a0 = aHH + (u32)(nt >> 1) * 1024u + (u32)(nt & 1) * 8u;
                sts64(a0,        f16x2(v[1], v[0]), f16x2(v[3], v[2]));
                sts64(a0 + 512u, f16x2(v[5], v[4]), f16x2(v[7], v[6]));
            }
        }

        // --- G2: h = silu(h @ w2 + b2)  (thread-local slots: in-place safe) ---
        {
            zeroN<8>(acc0); zeroN<8>(acc1);
            gemmF2<4, 4>(acc0, acc1, aHH, gW4 + OFF4_W2(l), 4, 0, 0, lane);
            const float* B2 = b2 + l * 64;
#pragma unroll
            for (int nt = 0; nt < 8; nt++){
                int c = nt * 8 + 2 * t;
                float2 bb = *(const float2*)(B2 + c);
                u32 a0 = aHH + (u32)(nt >> 1) * 1024u + (u32)(nt & 1) * 8u;
                sts64(a0, f16x2(silu_f(acc0[nt][1] + bb.y), silu_f(acc0[nt][0] + bb.x)),
                          f16x2(silu_f(acc0[nt][3] + bb.y), silu_f(acc0[nt][2] + bb.x)));
                sts64(a0 + 512u,
                          f16x2(silu_f(acc1[nt][1] + bb.y), silu_f(acc1[nt][0] + bb.x)),
                          f16x2(silu_f(acc1[nt][3] + bb.y), silu_f(acc1[nt][2] + bb.x)));
            }
        }

        // --- G3: ef += h @ w3 + b3 ; LN stats (4 rows/thread) ---
        {
            float s1[4] = {0,0,0,0}, s2[4] = {0,0,0,0};
            const float* B3 = b3 + l * 128;
#pragma unroll
            for (int p = 0; p < 2; p++){
                zeroN<8>(acc0); zeroN<8>(acc1);
                gemmF2<4, 4>(acc0, acc1, aHH, gW4 + OFF4_W3(l), 8, p * 4, 0, lane);
#pragma unroll
                for (int nt = 0; nt < 8; nt++){
                    int c = p * 64 + nt * 8 + 2 * t;
                    float2 bb = *(const float2*)(B3 + c);
                    int idx = p * 8 + nt;
                    u32 a0 = aEF + (u32)(idx >> 1) * 1024u + (u32)(idx & 1) * 8u;
#pragma unroll
                    for (int m = 0; m < 2; m++){
                        uint2 old = lds64(a0 + (u32)m * 512u);
                        float2 flo = h2f(old.x);
                        float2 fhi = h2f(old.y);
                        const float* A = m ? acc1[nt] : acc0[nt];
                        float v0 = flo.x + A[0] + bb.x;
                        float v1 = flo.y + A[1] + bb.y;
                        float v2 = fhi.x + A[2] + bb.x;
                        float v3 = fhi.y + A[3] + bb.y;
                        s1[2 * m]     += v0 + v1; s2[2 * m]     += v0 * v0 + v1 * v1;
                        s1[2 * m + 1] += v2 + v3; s2[2 * m + 1] += v2 * v2 + v3 * v3;
                        sts64(a0 + (u32)m * 512u, f16x2(v1, v0), f16x2(v3, v2));
                    }
                }
            }
            const u32 mm = 0xffffffffu;
#pragma unroll
            for (int k = 0; k < 4; k++){
                s1[k] += __shfl_xor_sync(mm, s1[k], 1);
                s1[k] += __shfl_xor_sync(mm, s1[k], 2);
                s2[k] += __shfl_xor_sync(mm, s2[k], 1);
                s2[k] += __shfl_xor_sync(mm, s2[k], 2);
                mu[k] = s1[k] * 0.0078125f;
                rs[k] = rsqrtf(s2[k] * 0.0078125f - mu[k] * mu[k] + 1e-5f);
            }
        }

        // --- G4: t1 = silu(sh @ tpw1 + tpb1)  (tpw1 k-shifted at pack time) ---
        {
            zeroN<8>(acc0); zeroN<8>(acc1);
            gemmF2<2, 4>(acc0, acc1, aFF, gW4 + OFF4_TP1(l), 4, 0, 0, lane);
            const float* TB = tpb1 + l * 64;
#pragma unroll
            for (int nt = 0; nt < 8; nt++){
                int c = nt * 8 + 2 * t;
                float2 bb = *(const float2*)(TB + c);
                u32 a0 = aHH + (u32)(nt >> 1) * 1024u + (u32)(nt & 1) * 8u;
                sts64(a0, f16x2(silu_f(acc0[nt][1] + bb.y), silu_f(acc0[nt][0] + bb.x)),
                          f16x2(silu_f(acc0[nt][3] + bb.y), silu_f(acc0[nt][2] + bb.x)));
                sts64(a0 + 512u,
                          f16x2(silu_f(acc1[nt][1] + bb.y), silu_f(acc1[nt][0] + bb.x)),
                          f16x2(silu_f(acc1[nt][3] + bb.y), silu_f(acc1[nt][2] + bb.x)));
            }
        }

        // --- G5: w = t1 @ tpw2 + tpb2 ; ef = LN(ef) * w ---
        {
            const float* TB = tpb2 + l * 128;
            const float* LG = ln_g + l * 128;
            const float* LB = ln_b + l * 128;
#pragma unroll
            for (int p = 0; p < 2; p++){
                zeroN<8>(acc0); zeroN<8>(acc1);
                gemmF2<4, 4>(acc0, acc1, aHH, gW4 + OFF4_TP2(l), 8, p * 4, 0, lane);
#pragma unroll
                for (int nt = 0; nt < 8; nt++){
                    int c = p * 64 + nt * 8 + 2 * t;
                    float2 bb = *(const float2*)(TB + c);
                    float2 lg = *(const float2*)(LG + c);
                    float2 lb = *(const float2*)(LB + c);
                    int idx = p * 8 + nt;
                    u32 a0 = aEF + (u32)(idx >> 1) * 1024u + (u32)(idx & 1) * 8u;
#pragma unroll
                    for (int m = 0; m < 2; m++){
                        uint2 old = lds64(a0 + (u32)m * 512u);
                        float2 flo = h2f(old.x);
                        float2 fhi = h2f(old.y);
                        const float* A = m ? acc1[nt] : acc0[nt];
                        float v0 = ((flo.x - mu[2*m])   * rs[2*m]   * lg.x + lb.x) * (A[0] + bb.x);
                        float v1 = ((flo.y - mu[2*m])   * rs[2*m]   * lg.y + lb.y) * (A[1] + bb.y);
                        float v2 = ((fhi.x - mu[2*m+1]) * rs[2*m+1] * lg.x + lb.x) * (A[2] + bb.x);
                        float v3 = ((fhi.y - mu[2*m+1]) * rs[2*m+1] * lg.y + lb.y) * (A[3] + bb.y);
                        sts64(a0 + (u32)m * 512u, f16x2(v1, v0), f16x2(v3, v2));
                    }
                }
            }
        }
        __syncthreads();   // keep warps phase-coherent for L1 reuse of gW4
    }

    // ========== head =========================================================
    // G6: h = silu(ef @ hw1 + hb1)
    {
        zeroN<8>(acc0); zeroN<8>(acc1);
        gemmF2<8, 4>(acc0, acc1, aEF, gW4 + OFF4_HW1, 4, 0, 0, lane);
#pragma unroll
        for (int nt = 0; nt < 8; nt++){
            int c = nt * 8 + 2 * t;
            float2 bb = *(const float2*)(hb1 + c);
            u32 a0 = aHH + (u32)(nt >> 1) * 1024u + (u32)(nt & 1) * 8u;
            sts64(a0, f16x2(silu_f(acc0[nt][1] + bb.y), silu_f(acc0[nt][0] + bb.x)),
                      f16x2(silu_f(acc0[nt][3] + bb.y), silu_f(acc0[nt][2] + bb.x)));
            sts64(a0 + 512u,
                      f16x2(silu_f(acc1[nt][1] + bb.y), silu_f(acc1[nt][0] + bb.x)),
                      f16x2(silu_f(acc1[nt][3] + bb.y), silu_f(acc1[nt][2] + bb.x)));
        }
    }

    // G7: q = silu(h @ hw2 + hb2); pe = q . hw3   (hb3 folded in finalize)
    double pes = 0.0;
    {
        float a40[4][4], a41[4][4];
        zeroN<4>(a40); zeroN<4>(a41);
        gemmF2<4, 2>(a40, a41, aHH, gW4 + OFF4_HW2, 2, 0, 0, lane);
        float pe[4] = {0.f, 0.f, 0.f, 0.f};
#pragma unroll
        for (int nt = 0; nt < 4; nt++){
            int c = nt * 8 + 2 * t;
            float2 bb = *(const float2*)(hb2 + c);
            float2 ww = *(const float2*)(hw3 + c);
            pe[0] += silu_f(a40[nt][0] + bb.x) * ww.x + silu_f(a40[nt][1] + bb.y) * ww.y;
            pe[1] += silu_f(a40[nt][2] + bb.x) * ww.x + silu_f(a40[nt][3] + bb.y) * ww.y;
            pe[2] += silu_f(a41[nt][0] + bb.x) * ww.x + silu_f(a41[nt][1] + bb.y) * ww.y;
            pe[3] += silu_f(a41[nt][2] + bb.x) * ww.x + silu_f(a41[nt][3] + bb.y) * ww.y;
        }
        const u32 mm = 0xffffffffu;
#pragma unroll
        for (int k = 0; k < 4; k++){
            pe[k] += __shfl_xor_sync(mm, pe[k], 1);
            pe[k] += __shfl_xor_sync(mm, pe[k], 2);
        }
        if (t == 0){
            int e0 = blockIdx.x * EPC + warp * 32 + g;
#pragma unroll
            for (int k = 0; k < 4; k++)
                if (e0 + 8 * k < E) pes += (double)pe[k];
        }
    }

    // ---------------- per-block deterministic reduction ----------------------
    __syncthreads();                       // FF region free -> reuse as double[]
    double* red = (double*)(smem);
    red[tid] = pes;
    __syncthreads();
#pragma unroll 1
    for (int off = TPB / 2; off > 0; off >>= 1){
        if (tid < off) red[tid] += red[tid + off];
        __syncthreads();
    }
    if (tid == 0) g_partial[blockIdx.x] = red[0];
}

// ---------------------------------------------------------------------------
// prep: fold node_emb through w_init / w1 per atom type (fp32 exact)
__global__ void prep_kernel(const float* __restrict__ node_emb,
                            const float* __restrict__ w_init,
                            const float* __restrict__ w1)
{
    __shared__ float emb[64];
    int tpe = blockIdx.x;
    if (threadIdx.x < 64) emb[threadIdx.x] = node_emb[tpe * 64 + threadIdx.x];
    __syncthreads();
    int c = threadIdx.x;
    if (c < 128){
        float s0 = 0.0f, s1 = 0.0f;
#pragma unroll 4
        for (int k = 0; k < 64; k++){
            float e = emb[k];
            s0 += e * __ldg(w_init + k * 128 + c);
            s1 += e * __ldg(w_init + (64 + k) * 128 + c);
        }
        gP0[tpe * 128 + c] = s0;
        gP1[tpe * 128 + c] = s1;
    }
    if (c < 64){
#pragma unroll 1
        for (int ls = 0; ls < 6; ls++){
            int l = ls >> 1, s = ls & 1;
            const float* W = w1 + l * 264 * 64 + (128 + s * 64) * 64;
            float r = 0.0f;
#pragma unroll 4
            for (int k = 0; k < 64; k++) r += emb[k] * __ldg(W + k * 64 + c);
            gR[(ls * 100 + tpe) * 64 + c] = r;
        }
    }
}

// ---------------------------------------------------------------------------
__global__ void final_kernel(const int *__restrict__ an,
                             const float *__restrict__ atomic_e,
                             const float *__restrict__ hb3,
                             float *__restrict__ out, int N, int nB, int E) {
    __shared__ double red[256];
    double s = 0.0;
    for (int i = threadIdx.x; i < nB; i += 256) s += g_partial[i];
    for (int i = threadIdx.x; i < N; i += 256)
        s += (double)__ldg(atomic_e + __ldg(an + i));
    if (threadIdx.x == 0) s += (double)E * (double)__ldg(hb3);
    red[threadIdx.x] = s;
    __syncthreads();
    for (int off = 128; off > 0; off >>= 1) {
        if (threadIdx.x < off) red[threadIdx.x] += red[threadIdx.x + off];
        __syncthreads();
    }
    if (threadIdx.x == 0) out[0] = (float)red[0];
}

// ---------------------------------------------------------------------------
extern "C" void kernel_launch(void *const *d_in, const int *in_sizes, int n_in,
                              void *d_out, int out_size) {
    (void)n_in; (void)out_size;
    const int   *an    = (const int *)d_in[0];
    const float *pos   = (const float *)d_in[1];
    const int   *eidx  = (const int *)d_in[2];
    const float *nemb  = (const float *)d_in[3];
    const float *ae    = (const float *)d_in[4];
    const float *w_init= (const float *)d_in[5];
    const float *b_init= (const float *)d_in[6];
    const float *w1    = (const float *)d_in[7];
    const float *b1    = (const float *)d_in[8];
    const float *w2    = (const float *)d_in[9];
    const float *b2    = (const float *)d_in[10];
    const float *w3    = (const float *)d_in[11];
    const float *b3    = (const float *)d_in[12];
    const float *lng   = (const float *)d_in[13];
    const float *lnb   = (const float *)d_in[14];
    const float *tpw1  = (const float *)d_in[15];
    const float *tpb1  = (const float *)d_in[16];
    const float *tpw2  = (const float *)d_in[17];
    const float *tpb2  = (const float *)d_in[18];
    const float *hw1   = (const float *)d_in[19];
    const float *hb1   = (const float *)d_in[20];
    const float *hw2   = (const float *)d_in[21];
    const float *hb2   = (const float *)d_in[22];
    const float *hw3   = (const float *)d_in[23];
    const float *hb3   = (const float *)d_in[24];

    const int N = in_sizes[0];
    const int E = in_sizes[2] / 2;
    int nB = (E + EPC - 1) / EPC;
    if (nB > 8192) nB = 8192;   // g_partial guard (800k edges -> 3125 blocks)

    cudaFuncSetAttribute(edge_kernel,
                         cudaFuncAttributeMaxDynamicSharedMemorySize, SM_TOTAL);

    round_kernel<<<(1568 + 127) / 128, 128>>>(w_init, w1, w2, w3,
                                              tpw1, tpw2, hw1, hw2);
    pack_frag_kernel<<<(PACK4_TOT + 255) / 256, 256>>>();
    prep_kernel<<<100, 128>>>(nemb, w_init, w1);
    edge_kernel<<<nB, TPB, SM_TOTAL>>>(
        an, pos, eidx, b_init, b1, b2, b3,
        lng, lnb, tpb1, tpb2, hb1, hb2, hw3, E);
    final_kernel<<<1, 256>>>(an, ae, hb3, (float *)d_out, N, nB, E);
}

// round 13
// speedup vs baseline: 1.0239x; 1.0239x over previous
#include <cuda_runtime.h>
#include <cuda_fp16.h>

typedef unsigned int u32;

#define TPB 256
#define EPC 256            // edges per CTA (8 warps x 32 rows)
#define FSTR 34            // fp32 feat scratch row stride (words)

#define SM_FF 0            // feat A-frags: 8w * 2ks * 2m * 512B = 16K
#define SM_EF 16384        // ef A-frags:   8w * 8ks * 2m * 512B = 64K (+scratch alias)
#define SM_TOTAL 81920

// ---- prepacked f16 weight image, uint4 = two n-adjacent B fragments ---------
#define PACK_TOT  27392
#define PACK4_TOT 13696
#define OFF4_WF      0
#define OFF4_W1(l)   (512   + (l) * 1152)
#define OFF4_W2(l)   (3968  + (l) * 512)
#define OFF4_W3(l)   (5504  + (l) * 1024)
#define OFF4_TP1(l)  (8576  + (l) * 256)
#define OFF4_TP2(l)  (9344  + (l) * 1024)
#define OFF4_HW1     12416
#define OFF4_HW2     13440

__device__ uint4  gW4[PACK4_TOT];
__device__ unsigned short gH[4 * PACK_TOT];   // canonical [seg][k][n] f16 image
__device__ double g_partial[8192];
__device__ float  gP0[100 * 128];
__device__ float  gP1[100 * 128];
__device__ float  gR [3 * 2 * 100 * 64];

__constant__ int c_soff[19] = {0, 1024, 3328, 5632, 7936, 8960, 9984,
                               11008, 13056, 15104, 17152, 17664, 18176,
                               18688, 20736, 22784, 24832, 26880, 27392};
__constant__ int c_soff4[19] = {0, 512, 1664, 2816, 3968, 4480, 4992,
                                5504, 6528, 7552, 8576, 8832, 9088,
                                9344, 10368, 11392, 12416, 13440, 13696};
__constant__ int c_ntg [18] = {16, 8,8,8, 8,8,8, 16,16,16, 8,8,8, 16,16,16, 8, 4};
__constant__ int c_n   [18] = {128, 64,64,64, 64,64,64, 128,128,128,
                               64,64,64, 128,128,128, 64, 32};
__constant__ int c_kreal[18]= {17, 136,136,136, 64,64,64, 64,64,64,
                               17,17,17, 64,64,64, 128, 64};
__constant__ int c_remap[18]= {0, 1,1,1, 0,0,0, 0,0,0, 2,2,2, 0,0,0, 0, 0};
__constant__ int c_src [18] = {0, 1,1,1, 2,2,2, 3,3,3, 4,4,4, 5,5,5, 6, 7};
__constant__ int c_woff[18] = {16384, 0,16896,33792, 0,4096,8192, 0,8192,16384,
                               0,576,1152, 0,8192,16384, 0, 0};
__constant__ int c_ncol[19] = {0, 128, 192, 256, 320, 384, 448, 512,
                               640, 768, 896, 960, 1024, 1088,
                               1216, 1344, 1472, 1536, 1568};

// ---------------- low-level helpers -----------------------------------------
__device__ __forceinline__ u32 smem_u32(const void* p){
    u32 a;
    asm("{ .reg .u64 t; cvta.to.shared.u64 t, %1; cvt.u32.u64 %0, t; }"
        : "=r"(a) : "l"(p));
    return a;
}
__device__ __forceinline__ float silu_f(float x){ return x / (1.0f + __expf(-x)); }
__device__ __forceinline__ void stsf(u32 a, float v){
    asm volatile("st.shared.f32 [%0], %1;" :: "r"(a), "f"(v));
}
__device__ __forceinline__ float2 ldsf2(u32 a){
    float2 v; asm volatile("ld.shared.v2.f32 {%0,%1}, [%2];"
                           : "=f"(v.x), "=f"(v.y) : "r"(a));
    return v;
}
__device__ __forceinline__ uint4 lds128(u32 a){
    uint4 v; asm volatile("ld.shared.v4.u32 {%0,%1,%2,%3}, [%4];"
        : "=r"(v.x), "=r"(v.y), "=r"(v.z), "=r"(v.w) : "r"(a));
    return v;
}
__device__ __forceinline__ uint2 lds64(u32 a){
    uint2 v; asm volatile("ld.shared.v2.u32 {%0,%1}, [%2];"
        : "=r"(v.x), "=r"(v.y) : "r"(a));
    return v;
}
__device__ __forceinline__ void sts64(u32 a, u32 x, u32 y){
    asm volatile("st.shared.v2.u32 [%0], {%1,%2};" :: "r"(a), "r"(x), "r"(y));
}
__device__ __forceinline__ void sts128(u32 a, u32 x, u32 y, u32 z, u32 w){
    asm volatile("st.shared.v4.u32 [%0], {%1,%2,%3,%4};"
                 :: "r"(a), "r"(x), "r"(y), "r"(z), "r"(w));
}
// pack two f32 -> f16x2 (first src lands in HIGH half)
__device__ __forceinline__ u32 f16x2(float hi, float lo){
    u32 r; asm("cvt.rn.f16x2.f32 %0, %1, %2;" : "=r"(r) : "f"(hi), "f"(lo));
    return r;
}
__device__ __forceinline__ float2 h2f(u32 v){
    float2 f;
    asm("{.reg .f16 l, h; mov.b32 {l, h}, %2; cvt.f32.f16 %0, l; cvt.f32.f16 %1, h;}"
        : "=f"(f.x), "=f"(f.y) : "r"(v));
    return f;
}
__device__ __forceinline__ void mma_f16(float* d, const u32* a, u32 b0, u32 b1){
    asm volatile("mma.sync.aligned.m16n8k16.row.col.f32.f16.f16.f32 "
        "{%0,%1,%2,%3}, {%4,%5,%6,%7}, {%8,%9}, {%0,%1,%2,%3};"
        : "+f"(d[0]), "+f"(d[1]), "+f"(d[2]), "+f"(d[3])
        : "r"(a[0]), "r"(a[1]), "r"(a[2]), "r"(a[3]), "r"(b0), "r"(b1));
}

__device__ __forceinline__ void zero4x2(float (*a0)[4], float (*a1)[4]){
#pragma unroll
    for (int i = 0; i < 4; i++)
#pragma unroll
        for (int j = 0; j < 4; j++){ a0[i][j] = 0.0f; a1[i][j] = 0.0f; }
}

// ---- warp GEMM pass: M=32, 32 output cols (2 B uint4), prefetched -----------
// A from smem frag slots: kstep s at aAddr + 2s*512 (m0) / +(2s+1)*512 (m1)
template<int NKS>
__device__ __forceinline__ void gemmE2(float (*acc0)[4], float (*acc1)[4],
                                       u32 aAddr, const uint4* __restrict__ B,
                                       int NTGP, int ntgp0, int ksB0, int lane){
    const uint4* bp = B + ((u32)ksB0 * NTGP + ntgp0) * 32 + lane;
    uint4 b0 = __ldg(bp), b1 = __ldg(bp + 32);
    uint4 a0 = lds128(aAddr), a1 = lds128(aAddr + 512u);
#pragma unroll
    for (int s = 0; s < NKS; s++){
        uint4 nb0, nb1, na0, na1;
        if (s + 1 < NKS){
            const uint4* np = bp + (u32)((s + 1) * NTGP) * 32;
            nb0 = __ldg(np); nb1 = __ldg(np + 32);
            na0 = lds128(aAddr + (u32)(2 * (s + 1))     * 512u);
            na1 = lds128(aAddr + (u32)(2 * (s + 1) + 1) * 512u);
        }
        u32 A0[4] = {a0.x, a0.y, a0.z, a0.w};
        u32 A1[4] = {a1.x, a1.y, a1.z, a1.w};
        mma_f16(acc0[0], A0, b0.x, b0.y);
        mma_f16(acc0[1], A0, b0.z, b0.w);
        mma_f16(acc0[2], A0, b1.x, b1.y);
        mma_f16(acc0[3], A0, b1.z, b1.w);
        mma_f16(acc1[0], A1, b0.x, b0.y);
        mma_f16(acc1[1], A1, b0.z, b0.w);
        mma_f16(acc1[2], A1, b1.x, b1.y);
        mma_f16(acc1[3], A1, b1.z, b1.w);
        if (s + 1 < NKS){ b0 = nb0; b1 = nb1; a0 = na0; a1 = na1; }
    }
}
// A from registers (hh frags): slot 2s = m0, 2s+1 = m1
template<int NKS>
__device__ __forceinline__ void gemmH2(float (*acc0)[4], float (*acc1)[4],
                                       const u32 (*hhr)[4],
                                       const uint4* __restrict__ B,
                                       int NTGP, int ntgp0, int lane){
    const uint4* bp = B + (u32)ntgp0 * 32 + lane;
    uint4 b0 = __ldg(bp), b1 = __ldg(bp + 32);
#pragma unroll
    for (int s = 0; s < NKS; s++){
        uint4 nb0, nb1;
        if (s + 1 < NKS){
            const uint4* np = bp + (u32)((s + 1) * NTGP) * 32;
            nb0 = __ldg(np); nb1 = __ldg(np + 32);
        }
        mma_f16(acc0[0], hhr[2 * s],     b0.x, b0.y);
        mma_f16(acc0[1], hhr[2 * s],     b0.z, b0.w);
        mma_f16(acc0[2], hhr[2 * s],     b1.x, b1.y);
        mma_f16(acc0[3], hhr[2 * s],     b1.z, b1.w);
        mma_f16(acc1[0], hhr[2 * s + 1], b0.x, b0.y);
        mma_f16(acc1[1], hhr[2 * s + 1], b0.z, b0.w);
        mma_f16(acc1[2], hhr[2 * s + 1], b1.x, b1.y);
        mma_f16(acc1[3], hhr[2 * s + 1], b1.z, b1.w);
        if (s + 1 < NKS){ b0 = nb0; b1 = nb1; }
    }
}

// write one (gi, m) D-quad into hh-style A-frag slot array
__device__ __forceinline__ void frag_put(u32 (*fr)[4], int gi, int m,
                                         float v0, float v1, float v2, float v3){
    u32* slot = fr[(gi >> 1) * 2 + m];
    if (gi & 1){ slot[2] = f16x2(v1, v0); slot[3] = f16x2(v3, v2); }
    else       { slot[0] = f16x2(v1, v0); slot[1] = f16x2(v3, v2); }
}

// ---------------------------------------------------------------------------
// round_kernel: cascade (error-feedback) rounding of each weight column to f16.
__global__ void round_kernel(const float* __restrict__ w_init,
                             const float* __restrict__ w1,
                             const float* __restrict__ w2,
                             const float* __restrict__ w3,
                             const float* __restrict__ tpw1,
                             const float* __restrict__ tpw2,
                             const float* __restrict__ hw1,
                             const float* __restrict__ hw2)
{
    int col = blockIdx.x * blockDim.x + threadIdx.x;
    if (col >= 1568) return;
    int s = 0;
    while (s + 1 < 18 && col >= c_ncol[s + 1]) s++;
    int n = col - c_ncol[s];
    const float* srcs[8] = {w_init, w1, w2, w3, tpw1, tpw2, hw1, hw2};
    const float* W = srcs[c_src[s]] + c_woff[s];
    int N = c_n[s], Kreal = c_kreal[s], remap = c_remap[s];
    int Kpad = 16 * ((c_soff[s + 1] - c_soff[s]) / (c_ntg[s] * 32));
    unsigned short* out = gH + 4 * c_soff[s];
    float e = 0.0f;
    for (int k = 0; k < Kpad; k++){
        int r = k;
        bool real = true;
        if (remap == 1){
            if (k < 128)      r = k;
            else if (k < 136) r = k + 128;
            else              real = false;
        } else if (remap == 2){           // tpw1: shifted by +8 (sh at cols 8..16)
            if (k >= 8 && k < 17) r = k - 8; else real = false;
        } else {
            if (k >= Kreal) real = false;
        }
        unsigned short q = 0;
        if (real){
            float tt = __ldg(W + r * N + n) + e;
            __half h = __float2half_rn(tt);
            e = tt - __half2float(h);
            q = __half_as_ushort(h);
        }
        out[k * N + n] = q;
    }
}

// pack_frag: gather rounded f16 into uint4 image (two n-adjacent fragments).
__global__ void pack_frag_kernel()
{
    int i = blockIdx.x * blockDim.x + threadIdx.x;
    if (i >= PACK4_TOT) return;
    int s = 0;
    while (s + 1 < 18 && i >= c_soff4[s + 1]) s++;
    int local = i - c_soff4[s];
    int lane = local & 31, rest = local >> 5;
    int NTGP = c_ntg[s] >> 1;
    int ntgp = rest % NTGP, ks = rest / NTGP;
    int t = lane & 3, g = lane >> 2;
    int N = c_n[s];
    const unsigned short* src = gH + 4 * c_soff[s];
    int k0 = ks * 16 + 2 * t;
    int n0 = (2 * ntgp) * 8 + g;
    int n1 = n0 + 8;
    u32 a0 = src[(k0    ) * N + n0], a1 = src[(k0 + 1) * N + n0];
    u32 a8 = src[(k0 + 8) * N + n0], a9 = src[(k0 + 9) * N + n0];
    u32 b0 = src[(k0    ) * N + n1], b1 = src[(k0 + 1) * N + n1];
    u32 b8 = src[(k0 + 8) * N + n1], b9 = src[(k0 + 9) * N + n1];
    uint4 o;
    o.x = a0 | (a1 << 16);
    o.y = a8 | (a9 << 16);
    o.z = b0 | (b1 << 16);
    o.w = b8 | (b9 << 16);
    gW4[i] = o;
}

// ---------------------------------------------------------------------------
__global__ __launch_bounds__(TPB, 2) void edge_kernel(
    const int *__restrict__ an, const float *__restrict__ pos,
    const int *__restrict__ eidx,
    const float *__restrict__ b_init,
    const float *__restrict__ b1, const float *__restrict__ b2,
    const float *__restrict__ b3,
    const float *__restrict__ ln_g, const float *__restrict__ ln_b,
    const float *__restrict__ tpb1, const float *__restrict__ tpb2,
    const float *__restrict__ hb1, const float *__restrict__ hb2,
    const float *__restrict__ hw3,
    int E)
{
    extern __shared__ char smem[];
    const u32 sb  = smem_u32(smem);
    const int tid = threadIdx.x;
    const int warp = tid >> 5, lane = tid & 31;
    const int g = lane >> 2, t = lane & 3;

    // ---------------- own edge: features into fp32 scratch (EF alias) --------
    int e = blockIdx.x * EPC + tid;
    if (e >= E) e = E - 1;
    int myTi, myTj;
    {
        const int rowi = eidx[e];
        const int coli = eidx[E + e];
        myTi = an[rowi];
        myTj = an[coli];
        const float vx = pos[3 * coli + 0] - pos[3 * rowi + 0];
        const float vy = pos[3 * coli + 1] - pos[3 * rowi + 1];
        const float vz = pos[3 * coli + 2] - pos[3 * rowi + 2];
        const float d = sqrtf(vx * vx + vy * vy + vz * vz);

        u32 r0 = sb + SM_EF + (u32)tid * (FSTR * 4);
        float env = (d < 5.0f) ? (0.5f * (cosf(d * 0.6283185307179586f) + 1.0f)) : 0.0f;
        const float cen[8] = { 0.98078528040323044f,  0.83146961230254524f,
                               0.55557023301960218f,  0.19509032201612825f,
                              -0.19509032201612825f, -0.55557023301960218f,
                              -0.83146961230254524f, -0.98078528040323044f};
#pragma unroll
        for (int i = 0; i < 8; i++){
            float z = (d - cen[i] * 5.0f) * 1.6f;
            stsf(r0 + i * 4, __expf(-0.5f * z * z) * env);
        }
        float r = fmaxf(d, 1e-8f);
        float inv = 1.0f / r;
        float ux = vx * inv, uy = vy * inv, uz = vz * inv;
        stsf(r0 +  8 * 4, 0.28209479177387814f);
        stsf(r0 +  9 * 4, -0.4886025119029199f * uy);
        stsf(r0 + 10 * 4,  0.4886025119029199f * uz);
        stsf(r0 + 11 * 4, -0.4886025119029199f * ux);
        stsf(r0 + 12 * 4,  1.0925484305920792f * ux * uy);
        stsf(r0 + 13 * 4, -1.0925484305920792f * uy * uz);
        stsf(r0 + 14 * 4,  0.94617469575756f * uz * uz
                          - 0.31539156525252f * (ux * ux + uy * uy));
        stsf(r0 + 15 * 4, -1.0925484305920792f * ux * uz);
        stsf(r0 + 16 * 4,  0.5462742152960396f * (ux * ux - uy * uy));
#pragma unroll
        for (int i = 17; i < 32; i++) stsf(r0 + i * 4, 0.0f);
    }
    __syncwarp();

    // atom types for this thread's 4 rows (row owner lane = local row index)
    int tiR[4], tjR[4];
#pragma unroll
    for (int k = 0; k < 4; k++){
        int src = g + 8 * k;
        tiR[k] = __shfl_sync(0xffffffffu, myTi, src);
        tjR[k] = __shfl_sync(0xffffffffu, myTj, src);
    }

    // pack featF A-fragments (warp-local; scratch rows owned by same warp)
    {
        u32 scr = sb + SM_EF;
        u32 ffW = sb + SM_FF + (u32)warp * 2048u;
#pragma unroll
        for (int ks = 0; ks < 2; ks++)
#pragma unroll
        for (int m = 0; m < 2; m++){
            int r0 = warp * 32 + m * 16 + g;
            u32 base = scr + ((u32)r0 * FSTR + (u32)(ks * 16 + 2 * t)) * 4u;
            float2 q0 = ldsf2(base);
            float2 q1 = ldsf2(base + 8u * FSTR * 4u);
            float2 q2 = ldsf2(base + 32u);
            float2 q3 = ldsf2(base + 8u * FSTR * 4u + 32u);
            sts128(ffW + (u32)(ks * 2 + m) * 512u + (u32)lane * 16u,
                   f16x2(q0.y, q0.x), f16x2(q1.y, q1.x),
                   f16x2(q2.y, q2.x), f16x2(q3.y, q3.x));
        }
    }
    __syncthreads();   // scratch dead everywhere before EF-frag writes

    const u32 aFF = sb + SM_FF + (u32)warp * 2048u + (u32)lane * 16u;
    const u32 aEF = sb + SM_EF + (u32)warp * 8192u + (u32)lane * 16u;

    u32   hhr[8][4];              // h as pre-packed A-frags (registers)
    float acc0[4][4], acc1[4][4];

    // ========== G0: ef = feat @ Wf + P0[ai] + P1[aj] + b_init (4 passes) =====
#pragma unroll
    for (int q = 0; q < 4; q++){
        zero4x2(acc0, acc1);
        gemmE2<2>(acc0, acc1, aFF, gW4 + OFF4_WF, 8, q * 2, 0, lane);
#pragma unroll
        for (int nt = 0; nt < 4; nt++){
            int c = q * 32 + nt * 8 + 2 * t;
            float2 bb = *(const float2*)(b_init + c);
            float v[8];
#pragma unroll
            for (int k = 0; k < 4; k++){
                float2 p0 = *(const float2*)(gP0 + tiR[k] * 128 + c);
                float2 p1 = *(const float2*)(gP1 + tjR[k] * 128 + c);
                const float* A = (k < 2) ? acc0[nt] : acc1[nt];
                v[2 * k]     = A[(k & 1) * 2]     + bb.x + p0.x + p1.x;
                v[2 * k + 1] = A[(k & 1) * 2 + 1] + bb.y + p0.y + p1.y;
            }
            int gi = q * 4 + nt;
            u32 a0 = aEF + (u32)(gi >> 1) * 1024u + (u32)(gi & 1) * 8u;
            sts64(a0,        f16x2(v[1], v[0]), f16x2(v[3], v[2]));
            sts64(a0 + 512u, f16x2(v[5], v[4]), f16x2(v[7], v[6]));
        }
    }

    float mu[4], rs[4];

    // ========== layers =======================================================
#pragma unroll 1
    for (int l = 0; l < 3; l++){
        // --- G1: h = silu(ef@W1a + rbf@W1b + R0[ai] + R1[aj] + b1) -> hhr ---
        {
            const uint4* B = gW4 + OFF4_W1(l);
            const float* B1 = b1 + l * 64;
            const float* R0b = gR + (l * 2    ) * 6400;
            const float* R1b = gR + (l * 2 + 1) * 6400;
#pragma unroll
            for (int q = 0; q < 2; q++){
                zero4x2(acc0, acc1);
                gemmE2<8>(acc0, acc1, aEF, B, 4, q * 2, 0, lane);
                gemmE2<1>(acc0, acc1, aFF, B, 4, q * 2, 8, lane);  // rbf tail
#pragma unroll
                for (int nt = 0; nt < 4; nt++){
                    int c = q * 32 + nt * 8 + 2 * t;
                    float2 bb = *(const float2*)(B1 + c);
                    float v[8];
#pragma unroll
                    for (int k = 0; k < 4; k++){
                        float2 x0 = *(const float2*)(R0b + tiR[k] * 64 + c);
                        float2 x1 = *(const float2*)(R1b + tjR[k] * 64 + c);
                        const float* A = (k < 2) ? acc0[nt] : acc1[nt];
                        v[2 * k]     = silu_f(A[(k & 1) * 2]     + bb.x + x0.x + x1.x);
                        v[2 * k + 1] = silu_f(A[(k & 1) * 2 + 1] + bb.y + x0.y + x1.y);
                    }
                    int gi = q * 4 + nt;
                    frag_put(hhr, gi, 0, v[0], v[1], v[2], v[3]);
                    frag_put(hhr, gi, 1, v[4], v[5], v[6], v[7]);
                }
            }
        }

        // --- G2: h = silu(h @ w2 + b2)  (pass0 -> tmp, commit after pass1) ---
        {
            const float* B2 = b2 + l * 64;
            u32 tmp[4][4];
#pragma unroll
            for (int q = 0; q < 2; q++){
                zero4x2(acc0, acc1);
                gemmH2<4>(acc0, acc1, hhr, gW4 + OFF4_W2(l), 4, q * 2, lane);
#pragma unroll
                for (int nt = 0; nt < 4; nt++){
                    int c = q * 32 + nt * 8 + 2 * t;
                    float2 bb = *(const float2*)(B2 + c);
                    float v0 = silu_f(acc0[nt][0] + bb.x);
                    float v1 = silu_f(acc0[nt][1] + bb.y);
                    float v2 = silu_f(acc0[nt][2] + bb.x);
                    float v3 = silu_f(acc0[nt][3] + bb.y);
                    float w0 = silu_f(acc1[nt][0] + bb.x);
                    float w1 = silu_f(acc1[nt][1] + bb.y);
                    float w2v= silu_f(acc1[nt][2] + bb.x);
                    float w3v= silu_f(acc1[nt][3] + bb.y);
                    if (q == 0){
                        frag_put(tmp, nt, 0, v0, v1, v2, v3);
                        frag_put(tmp, nt, 1, w0, w1, w2v, w3v);
                    } else {
                        frag_put(hhr, 4 + nt, 0, v0, v1, v2, v3);
                        frag_put(hhr, 4 + nt, 1, w0, w1, w2v, w3v);
                    }
                }
            }
#pragma unroll
            for (int i = 0; i < 4; i++)
#pragma unroll
                for (int j = 0; j < 4; j++) hhr[i][j] = tmp[i][j];
        }

        // --- G3: ef += h @ w3 + b3 ; LN stats (4 passes) ---
        {
            float s1[4] = {0,0,0,0}, s2[4] = {0,0,0,0};
            const float* B3 = b3 + l * 128;
#pragma unroll
            for (int q = 0; q < 4; q++){
                zero4x2(acc0, acc1);
                gemmH2<4>(acc0, acc1, hhr, gW4 + OFF4_W3(l), 8, q * 2, lane);
#pragma unroll
                for (int nt = 0; nt < 4; nt++){
                    int c = q * 32 + nt * 8 + 2 * t;
                    float2 bb = *(const float2*)(B3 + c);
                    int gi = q * 4 + nt;
                    u32 a0 = aEF + (u32)(gi >> 1) * 1024u + (u32)(gi & 1) * 8u;
#pragma unroll
                    for (int m = 0; m < 2; m++){
                        uint2 old = lds64(a0 + (u32)m * 512u);
                        float2 flo = h2f(old.x);
                        float2 fhi = h2f(old.y);
                        const float* A = m ? acc1[nt] : acc0[nt];
                        float v0 = flo.x + A[0] + bb.x;
                        float v1 = flo.y + A[1] + bb.y;
                        float v2 = fhi.x + A[2] + bb.x;
                        float v3 = fhi.y + A[3] + bb.y;
                        s1[2 * m]     += v0 + v1; s2[2 * m]     += v0 * v0 + v1 * v1;
                        s1[2 * m + 1] += v2 + v3; s2[2 * m + 1] += v2 * v2 + v3 * v3;
                        sts64(a0 + (u32)m * 512u, f16x2(v1, v0), f16x2(v3, v2));
                    }
                }
            }
            const u32 mm = 0xffffffffu;
#pragma unroll
            for (int k = 0; k < 4; k++){
                s1[k] += __shfl_xor_sync(mm, s1[k], 1);
                s1[k] += __shfl_xor_sync(mm, s1[k], 2);
                s2[k] += __shfl_xor_sync(mm, s2[k], 1);
                s2[k] += __shfl_xor_sync(mm, s2[k], 2);
                mu[k] = s1[k] * 0.0078125f;
                rs[k] = rsqrtf(s2[k] * 0.0078125f - mu[k] * mu[k] + 1e-5f);
            }
        }

        // --- G4: t1 = silu(sh @ tpw1 + tpb1)  -> hhr (no read hazard) ---
        {
            const float* TB = tpb1 + l * 64;
#pragma unroll
            for (int q = 0; q < 2; q++){
                zero4x2(acc0, acc1);
                gemmE2<2>(acc0, acc1, aFF, gW4 + OFF4_TP1(l), 4, q * 2, 0, lane);
#pragma unroll
                for (int nt = 0; nt < 4; nt++){
                    int c = q * 32 + nt * 8 + 2 * t;
                    float2 bb = *(const float2*)(TB + c);
                    int gi = q * 4 + nt;
                    frag_put(hhr, gi, 0, silu_f(acc0[nt][0] + bb.x),
                                         silu_f(acc0[nt][1] + bb.y),
                                         silu_f(acc0[nt][2] + bb.x),
                                         silu_f(acc0[nt][3] + bb.y));
                    frag_put(hhr, gi, 1, silu_f(acc1[nt][0] + bb.x),
                                         silu_f(acc1[nt][1] + bb.y),
                                         silu_f(acc1[nt][2] + bb.x),
                                         silu_f(acc1[nt][3] + bb.y));
                }
            }
        }

        // --- G5: w = t1 @ tpw2 + tpb2 ; ef = LN(ef) * w (4 passes) ---
        {
            const float* TB = tpb2 + l * 128;
            const float* LG = ln_g + l * 128;
            const float* LB = ln_b + l * 128;
#pragma unroll
            for (int q = 0; q < 4; q++){
                zero4x2(acc0, acc1);
                gemmH2<4>(acc0, acc1, hhr, gW4 + OFF4_TP2(l), 8, q * 2, lane);
#pragma unroll
                for (int nt = 0; nt < 4; nt++){
                    int c = q * 32 + nt * 8 + 2 * t;
                    float2 bb = *(const float2*)(TB + c);
                    float2 lg = *(const float2*)(LG + c);
                    float2 lb = *(const float2*)(LB + c);
                    int gi = q * 4 + nt;
                    u32 a0 = aEF + (u32)(gi >> 1) * 1024u + (u32)(gi & 1) * 8u;
#pragma unroll
                    for (int m = 0; m < 2; m++){
                        uint2 old = lds64(a0 + (u32)m * 512u);
                        float2 flo = h2f(old.x);
                        float2 fhi = h2f(old.y);
                        const float* A = m ? acc1[nt] : acc0[nt];
                        float v0 = ((flo.x - mu[2*m])   * rs[2*m]   * lg.x + lb.x) * (A[0] + bb.x);
                        float v1 = ((flo.y - mu[2*m])   * rs[2*m]   * lg.y + lb.y) * (A[1] + bb.y);
                        float v2 = ((fhi.x - mu[2*m+1]) * rs[2*m+1] * lg.x + lb.x) * (A[2] + bb.x);
                        float v3 = ((fhi.y - mu[2*m+1]) * rs[2*m+1] * lg.y + lb.y) * (A[3] + bb.y);
                        sts64(a0 + (u32)m * 512u, f16x2(v1, v0), f16x2(v3, v2));
                    }
                }
            }
        }
        __syncthreads();   // keep warps phase-coherent for L1 reuse of gW4
    }

    // ========== head =========================================================
    // G6: h = silu(ef @ hw1 + hb1) -> hhr
#pragma unroll
    for (int q = 0; q < 2; q++){
        zero4x2(acc0, acc1);
        gemmE2<8>(acc0, acc1, aEF, gW4 + OFF4_HW1, 4, q * 2, 0, lane);
#pragma unroll
        for (int nt = 0; nt < 4; nt++){
            int c = q * 32 + nt * 8 + 2 * t;
            float2 bb = *(const float2*)(hb1 + c);
            int gi = q * 4 + nt;
            frag_put(hhr, gi, 0, silu_f(acc0[nt][0] + bb.x),
                                 silu_f(acc0[nt][1] + bb.y),
                                 silu_f(acc0[nt][2] + bb.x),
                                 silu_f(acc0[nt][3] + bb.y));
            frag_put(hhr, gi, 1, silu_f(acc1[nt][0] + bb.x),
                                 silu_f(acc1[nt][1] + bb.y),
                                 silu_f(acc1[nt][2] + bb.x),
                                 silu_f(acc1[nt][3] + bb.y));
        }
    }

    // G7: q = silu(h @ hw2 + hb2); pe = q . hw3   (hb3 folded in finalize)
    double pes = 0.0;
    {
        zero4x2(acc0, acc1);
        gemmH2<4>(acc0, acc1, hhr, gW4 + OFF4_HW2, 2, 0, lane);
        float pe[4] = {0.f, 0.f, 0.f, 0.f};
#pragma unroll
        for (int nt = 0; nt < 4; nt++){
            int c = nt * 8 + 2 * t;
            float2 bb = *(const float2*)(hb2 + c);
            float2 ww = *(const float2*)(hw3 + c);
            pe[0] += silu_f(acc0[nt][0] + bb.x) * ww.x + silu_f(acc0[nt][1] + bb.y) * ww.y;
            pe[1] += silu_f(acc0[nt][2] + bb.x) * ww.x + silu_f(acc0[nt][3] + bb.y) * ww.y;
            pe[2] += silu_f(acc1[nt][0] + bb.x) * ww.x + silu_f(acc1[nt][1] + bb.y) * ww.y;
            pe[3] += silu_f(acc1[nt][2] + bb.x) * ww.x + silu_f(acc1[nt][3] + bb.y) * ww.y;
        }
        const u32 mm = 0xffffffffu;
#pragma unroll
        for (int k = 0; k < 4; k++){
            pe[k] += __shfl_xor_sync(mm, pe[k], 1);
            pe[k] += __shfl_xor_sync(mm, pe[k], 2);
        }
        if (t == 0){
            int e0 = blockIdx.x * EPC + warp * 32 + g;
#pragma unroll
            for (int k = 0; k < 4; k++)
                if (e0 + 8 * k < E) pes += (double)pe[k];
        }
    }

    // ---------------- per-block deterministic reduction ----------------------
    __syncthreads();                       // FF region free -> reuse as double[]
    double* red = (double*)(smem);
    red[tid] = pes;
    __syncthreads();
#pragma unroll 1
    for (int off = TPB / 2; off > 0; off >>= 1){
        if (tid < off) red[tid] += red[tid + off];
        __syncthreads();
    }
    if (tid == 0) g_partial[blockIdx.x] = red[0];
}

// ---------------------------------------------------------------------------
// prep: fold node_emb through w_init / w1 per atom type (fp32 exact)
__global__ void prep_kernel(const float* __restrict__ node_emb,
                            const float* __restrict__ w_init,
                            const float* __restrict__ w1)
{
    __shared__ float emb[64];
    int tpe = blockIdx.x;
    if (threadIdx.x < 64) emb[threadIdx.x] = node_emb[tpe * 64 + threadIdx.x];
    __syncthreads();
    int c = threadIdx.x;
    if (c < 128){
        float s0 = 0.0f, s1 = 0.0f;
#pragma unroll 4
        for (int k = 0; k < 64; k++){
            float e = emb[k];
            s0 += e * __ldg(w_init + k * 128 + c);
            s1 += e * __ldg(w_init + (64 + k) * 128 + c);
        }
        gP0[tpe * 128 + c] = s0;
        gP1[tpe * 128 + c] = s1;
    }
    if (c < 64){
#pragma unroll 1
        for (int ls = 0; ls < 6; ls++){
            int l = ls >> 1, s = ls & 1;
            const float* W = w1 + l * 264 * 64 + (128 + s * 64) * 64;
            float r = 0.0f;
#pragma unroll 4
            for (int k = 0; k < 64; k++) r += emb[k] * __ldg(W + k * 64 + c);
            gR[(ls * 100 + tpe) * 64 + c] = r;
        }
    }
}

// ---------------------------------------------------------------------------
__global__ void final_kernel(const int *__restrict__ an,
                             const float *__restrict__ atomic_e,
                             const float *__restrict__ hb3,
                             float *__restrict__ out, int N, int nB, int E) {
    __shared__ double red[256];
    double s = 0.0;
    for (int i = threadIdx.x; i < nB; i += 256) s += g_partial[i];
    for (int i = threadIdx.x; i < N; i += 256)
        s += (double)__ldg(atomic_e + __ldg(an + i));
    if (threadIdx.x == 0) s += (double)E * (double)__ldg(hb3);
    red[threadIdx.x] = s;
    __syncthreads();
    for (int off = 128; off > 0; off >>= 1) {
        if (threadIdx.x < off) red[threadIdx.x] += red[threadIdx.x + off];
        __syncthreads();
    }
    if (threadIdx.x == 0) out[0] = (float)red[0];
}

// ---------------------------------------------------------------------------
extern "C" void kernel_launch(void *const *d_in, const int *in_sizes, int n_in,
                              void *d_out, int out_size) {
    (void)n_in; (void)out_size;
    const int   *an    = (const int *)d_in[0];
    const float *pos   = (const float *)d_in[1];
    const int   *eidx  = (const int *)d_in[2];
    const float *nemb  = (const float *)d_in[3];
    const float *ae    = (const float *)d_in[4];
    const float *w_init= (const float *)d_in[5];
    const float *b_init= (const float *)d_in[6];
    const float *w1    = (const float *)d_in[7];
    const float *b1    = (const float *)d_in[8];
    const float *w2    = (const float *)d_in[9];
    const float *b2    = (const float *)d_in[10];
    const float *w3    = (const float *)d_in[11];
    const float *b3    = (const float *)d_in[12];
    const float *lng   = (const float *)d_in[13];
    const float *lnb   = (const float *)d_in[14];
    const float *tpw1  = (const float *)d_in[15];
    const float *tpb1  = (const float *)d_in[16];
    const float *tpw2  = (const float *)d_in[17];
    const float *tpb2  = (const float *)d_in[18];
    const float *hw1   = (const float *)d_in[19];
    const float *hb1   = (const float *)d_in[20];
    const float *hw2   = (const float *)d_in[21];
    const float *hb2   = (const float *)d_in[22];
    const float *hw3   = (const float *)d_in[23];
    const float *hb3   = (const float *)d_in[24];

    const int N = in_sizes[0];
    const int E = in_sizes[2] / 2;
    int nB = (E + EPC - 1) / EPC;
    if (nB > 8192) nB = 8192;   // g_partial guard (800k edges -> 3125 blocks)

    cudaFuncSetAttribute(edge_kernel,
                         cudaFuncAttributeMaxDynamicSharedMemorySize, SM_TOTAL);

    round_kernel<<<(1568 + 127) / 128, 128>>>(w_init, w1, w2, w3,
                                              tpw1, tpw2, hw1, hw2);
    pack_frag_kernel<<<(PACK4_TOT + 255) / 256, 256>>>();
    prep_kernel<<<100, 128>>>(nemb, w_init, w1);
    edge_kernel<<<nB, TPB, SM_TOTAL>>>(
        an, pos, eidx, b_init, b1, b2, b3,
        lng, lnb, tpb1, tpb2, hb1, hb2, hw3, E);
    final_kernel<<<1, 256>>>(an, ae, hb3, (float *)d_out, N, nB, E);
}

// round 14
// speedup vs baseline: 1.0992x; 1.0735x over previous
#include <cuda_runtime.h>
#include <cuda_fp16.h>

typedef unsigned int u32;

#define TPB 224
#define EPC 112            // edges per CTA (7 warps x 16 rows)
#define FSTR 34            // fp32 feat scratch row stride (words)

#define SM_FF 0            // feat A-frags: 7w * 2ks * 512B = 7168
#define SM_EF 7168         // ef A-frags: 7w * 8ks * 512B = 28672 (+scratch alias)
#define SM_HH 35840        // h  A-frags: 7w * 4ks * 512B = 14336
#define SM_AI 50176        // 112 * 4
#define SM_AJ 50624
#define SM_TOTAL 51072

// ---- prepacked f16 weight image, uint4 = two n-adjacent B fragments ---------
#define PACK_TOT  27392
#define PACK4_TOT 13696
#define OFF4_WF      0
#define OFF4_W1(l)   (512   + (l) * 1152)
#define OFF4_W2(l)   (3968  + (l) * 512)
#define OFF4_W3(l)   (5504  + (l) * 1024)
#define OFF4_TP1(l)  (8576  + (l) * 256)
#define OFF4_TP2(l)  (9344  + (l) * 1024)
#define OFF4_HW1     12416
#define OFF4_HW2     13440

__device__ uint4  gW4[PACK4_TOT];
__device__ unsigned short gH[4 * PACK_TOT];   // canonical [seg][k][n] f16 image
__device__ double g_partial[8192];
__device__ float  gP0[100 * 128];
__device__ float  gP1[100 * 128];
__device__ float  gR [3 * 2 * 100 * 64];

__constant__ int c_soff[19] = {0, 1024, 3328, 5632, 7936, 8960, 9984,
                               11008, 13056, 15104, 17152, 17664, 18176,
                               18688, 20736, 22784, 24832, 26880, 27392};
__constant__ int c_soff4[19] = {0, 512, 1664, 2816, 3968, 4480, 4992,
                                5504, 6528, 7552, 8576, 8832, 9088,
                                9344, 10368, 11392, 12416, 13440, 13696};
__constant__ int c_ntg [18] = {16, 8,8,8, 8,8,8, 16,16,16, 8,8,8, 16,16,16, 8, 4};
__constant__ int c_n   [18] = {128, 64,64,64, 64,64,64, 128,128,128,
                               64,64,64, 128,128,128, 64, 32};
__constant__ int c_kreal[18]= {17, 136,136,136, 64,64,64, 64,64,64,
                               17,17,17, 64,64,64, 128, 64};
__constant__ int c_remap[18]= {0, 1,1,1, 0,0,0, 0,0,0, 2,2,2, 0,0,0, 0, 0};
__constant__ int c_src [18] = {0, 1,1,1, 2,2,2, 3,3,3, 4,4,4, 5,5,5, 6, 7};
__constant__ int c_woff[18] = {16384, 0,16896,33792, 0,4096,8192, 0,8192,16384,
                               0,576,1152, 0,8192,16384, 0, 0};
__constant__ int c_ncol[19] = {0, 128, 192, 256, 320, 384, 448, 512,
                               640, 768, 896, 960, 1024, 1088,
                               1216, 1344, 1472, 1536, 1568};

// ---------------- low-level helpers -----------------------------------------
__device__ __forceinline__ u32 smem_u32(const void* p){
    u32 a;
    asm("{ .reg .u64 t; cvta.to.shared.u64 t, %1; cvt.u32.u64 %0, t; }"
        : "=r"(a) : "l"(p));
    return a;
}
__device__ __forceinline__ float silu_f(float x){ return x / (1.0f + __expf(-x)); }
__device__ __forceinline__ int ldsi(u32 a){
    int v; asm volatile("ld.shared.b32 %0, [%1];" : "=r"(v) : "r"(a)); return v;
}
__device__ __forceinline__ void stsf(u32 a, float v){
    asm volatile("st.shared.f32 [%0], %1;" :: "r"(a), "f"(v));
}
__device__ __forceinline__ void stsi(u32 a, int v){
    asm volatile("st.shared.b32 [%0], %1;" :: "r"(a), "r"(v));
}
__device__ __forceinline__ float2 ldsf2(u32 a){
    float2 v; asm volatile("ld.shared.v2.f32 {%0,%1}, [%2];"
                           : "=f"(v.x), "=f"(v.y) : "r"(a));
    return v;
}
__device__ __forceinline__ uint4 lds128(u32 a){
    uint4 v; asm volatile("ld.shared.v4.u32 {%0,%1,%2,%3}, [%4];"
        : "=r"(v.x), "=r"(v.y), "=r"(v.z), "=r"(v.w) : "r"(a));
    return v;
}
__device__ __forceinline__ uint2 lds64(u32 a){
    uint2 v; asm volatile("ld.shared.v2.u32 {%0,%1}, [%2];"
        : "=r"(v.x), "=r"(v.y) : "r"(a));
    return v;
}
__device__ __forceinline__ void sts64(u32 a, u32 x, u32 y){
    asm volatile("st.shared.v2.u32 [%0], {%1,%2};" :: "r"(a), "r"(x), "r"(y));
}
__device__ __forceinline__ void sts128(u32 a, u32 x, u32 y, u32 z, u32 w){
    asm volatile("st.shared.v4.u32 [%0], {%1,%2,%3,%4};"
                 :: "r"(a), "r"(x), "r"(y), "r"(z), "r"(w));
}
// pack two f32 -> f16x2 (first src lands in HIGH half)
__device__ __forceinline__ u32 f16x2(float hi, float lo){
    u32 r; asm("cvt.rn.f16x2.f32 %0, %1, %2;" : "=r"(r) : "f"(hi), "f"(lo));
    return r;
}
__device__ __forceinline__ float2 h2f(u32 v){
    float2 f;
    asm("{.reg .f16 l, h; mov.b32 {l, h}, %2; cvt.f32.f16 %0, l; cvt.f32.f16 %1, h;}"
        : "=f"(f.x), "=f"(f.y) : "r"(v));
    return f;
}
__device__ __forceinline__ void mma_f16(float* d, const u32* a, u32 b0, u32 b1){
    asm volatile("mma.sync.aligned.m16n8k16.row.col.f32.f16.f16.f32 "
        "{%0,%1,%2,%3}, {%4,%5,%6,%7}, {%8,%9}, {%0,%1,%2,%3};"
        : "+f"(d[0]), "+f"(d[1]), "+f"(d[2]), "+f"(d[3])
        : "r"(a[0]), "r"(a[1]), "r"(a[2]), "r"(a[3]), "r"(b0), "r"(b1));
}

template<int NT>
__device__ __forceinline__ void zeroN(float (*a)[4]){
#pragma unroll
    for (int i = 0; i < NT; i++)
#pragma unroll
        for (int j = 0; j < 4; j++) a[i][j] = 0.0f;
}

// ---- warp GEMM (M=16): A frag slots in smem (512B/kstep), B uint4 pairs -----
template<int NKS, int NTP>
__device__ __forceinline__ void gemmA(float (*acc)[4], u32 aSlots,
                                      const uint4* __restrict__ B,
                                      int NTGP, int ntgp0, int ksB0, int lane){
#pragma unroll
    for (int s = 0; s < NKS; s++){
        uint4 av = lds128(aSlots + (u32)s * 512u);
        u32 a[4] = {av.x, av.y, av.z, av.w};
        const uint4* bp = B + ((u32)(ksB0 + s) * NTGP + ntgp0) * 32 + lane;
#pragma unroll
        for (int p = 0; p < NTP; p++){
            uint4 b = __ldg(bp + p * 32);
            mma_f16(acc[2 * p],     a, b.x, b.y);
            mma_f16(acc[2 * p + 1], a, b.z, b.w);
        }
    }
}

// ---------------------------------------------------------------------------
// round_kernel: cascade (error-feedback) rounding of each weight column to f16.
__global__ void round_kernel(const float* __restrict__ w_init,
                             const float* __restrict__ w1,
                             const float* __restrict__ w2,
                             const float* __restrict__ w3,
                             const float* __restrict__ tpw1,
                             const float* __restrict__ tpw2,
                             const float* __restrict__ hw1,
                             const float* __restrict__ hw2)
{
    int col = blockIdx.x * blockDim.x + threadIdx.x;
    if (col >= 1568) return;
    int s = 0;
    while (s + 1 < 18 && col >= c_ncol[s + 1]) s++;
    int n = col - c_ncol[s];
    const float* srcs[8] = {w_init, w1, w2, w3, tpw1, tpw2, hw1, hw2};
    const float* W = srcs[c_src[s]] + c_woff[s];
    int N = c_n[s], Kreal = c_kreal[s], remap = c_remap[s];
    int Kpad = 16 * ((c_soff[s + 1] - c_soff[s]) / (c_ntg[s] * 32));
    unsigned short* out = gH + 4 * c_soff[s];
    float e = 0.0f;
    for (int k = 0; k < Kpad; k++){
        int r = k;
        bool real = true;
        if (remap == 1){
            if (k < 128)      r = k;
            else if (k < 136) r = k + 128;
            else              real = false;
        } else if (remap == 2){           // tpw1: shifted by +8 (sh at cols 8..16)
            if (k >= 8 && k < 17) r = k - 8; else real = false;
        } else {
            if (k >= Kreal) real = false;
        }
        unsigned short q = 0;
        if (real){
            float tt = __ldg(W + r * N + n) + e;
            __half h = __float2half_rn(tt);
            e = tt - __half2float(h);
            q = __half_as_ushort(h);
        }
        out[k * N + n] = q;
    }
}

// pack_frag: gather rounded f16 into uint4 image (two n-adjacent fragments).
__global__ void pack_frag_kernel()
{
    int i = blockIdx.x * blockDim.x + threadIdx.x;
    if (i >= PACK4_TOT) return;
    int s = 0;
    while (s + 1 < 18 && i >= c_soff4[s + 1]) s++;
    int local = i - c_soff4[s];
    int lane = local & 31, rest = local >> 5;
    int NTGP = c_ntg[s] >> 1;
    int ntgp = rest % NTGP, ks = rest / NTGP;
    int t = lane & 3, g = lane >> 2;
    int N = c_n[s];
    const unsigned short* src = gH + 4 * c_soff[s];
    int k0 = ks * 16 + 2 * t;
    int n0 = (2 * ntgp) * 8 + g;
    int n1 = n0 + 8;
    u32 a0 = src[(k0    ) * N + n0], a1 = src[(k0 + 1) * N + n0];
    u32 a8 = src[(k0 + 8) * N + n0], a9 = src[(k0 + 9) * N + n0];
    u32 b0 = src[(k0    ) * N + n1], b1 = src[(k0 + 1) * N + n1];
    u32 b8 = src[(k0 + 8) * N + n1], b9 = src[(k0 + 9) * N + n1];
    uint4 o;
    o.x = a0 | (a1 << 16);
    o.y = a8 | (a9 << 16);
    o.z = b0 | (b1 << 16);
    o.w = b8 | (b9 << 16);
    gW4[i] = o;
}

// ---------------------------------------------------------------------------
__global__ __launch_bounds__(TPB, 4) void edge_kernel(
    const int *__restrict__ an, const float *__restrict__ pos,
    const int *__restrict__ eidx,
    const float *__restrict__ b_init,
    const float *__restrict__ b1, const float *__restrict__ b2,
    const float *__restrict__ b3,
    const float *__restrict__ ln_g, const float *__restrict__ ln_b,
    const float *__restrict__ tpb1, const float *__restrict__ tpb2,
    const float *__restrict__ hb1, const float *__restrict__ hb2,
    const float *__restrict__ hw3,
    int E)
{
    extern __shared__ char smem[];
    const u32 sb  = smem_u32(smem);
    const int tid = threadIdx.x;
    const int warp = tid >> 5, lane = tid & 31;
    const int g = lane >> 2, t = lane & 3;
    const int woff16 = warp * 16;

    // ---------------- per-edge features (threads 0..111) into fp32 scratch ---
    if (tid < EPC){
        int e = blockIdx.x * EPC + tid;
        if (e >= E) e = E - 1;
        const int rowi = eidx[e];
        const int coli = eidx[E + e];
        const float vx = pos[3 * coli + 0] - pos[3 * rowi + 0];
        const float vy = pos[3 * coli + 1] - pos[3 * rowi + 1];
        const float vz = pos[3 * coli + 2] - pos[3 * rowi + 2];
        const float d = sqrtf(vx * vx + vy * vy + vz * vz);

        u32 r0 = sb + SM_EF + (u32)tid * (FSTR * 4);   // scratch aliases EF
        float env = (d < 5.0f) ? (0.5f * (cosf(d * 0.6283185307179586f) + 1.0f)) : 0.0f;
        const float cen[8] = { 0.98078528040323044f,  0.83146961230254524f,
                               0.55557023301960218f,  0.19509032201612825f,
                              -0.19509032201612825f, -0.55557023301960218f,
                              -0.83146961230254524f, -0.98078528040323044f};
#pragma unroll
        for (int i = 0; i < 8; i++){
            float z = (d - cen[i] * 5.0f) * 1.6f;
            stsf(r0 + i * 4, __expf(-0.5f * z * z) * env);
        }
        float r = fmaxf(d, 1e-8f);
        float inv = 1.0f / r;
        float ux = vx * inv, uy = vy * inv, uz = vz * inv;
        stsf(r0 +  8 * 4, 0.28209479177387814f);
        stsf(r0 +  9 * 4, -0.4886025119029199f * uy);
        stsf(r0 + 10 * 4,  0.4886025119029199f * uz);
        stsf(r0 + 11 * 4, -0.4886025119029199f * ux);
        stsf(r0 + 12 * 4,  1.0925484305920792f * ux * uy);
        stsf(r0 + 13 * 4, -1.0925484305920792f * uy * uz);
        stsf(r0 + 14 * 4,  0.94617469575756f * uz * uz
                          - 0.31539156525252f * (ux * ux + uy * uy));
        stsf(r0 + 15 * 4, -1.0925484305920792f * ux * uz);
        stsf(r0 + 16 * 4,  0.5462742152960396f * (ux * ux - uy * uy));
#pragma unroll
        for (int i = 17; i < 32; i++) stsf(r0 + i * 4, 0.0f);
        stsi(sb + SM_AI + tid * 4, an[rowi]);
        stsi(sb + SM_AJ + tid * 4, an[coli]);
    }
    __syncthreads();

    const int r0loc = woff16 + g;
    const int ti0 = ldsi(sb + SM_AI + r0loc * 4);
    const int tj0 = ldsi(sb + SM_AJ + r0loc * 4);
    const int ti1 = ldsi(sb + SM_AI + (r0loc + 8) * 4);
    const int tj1 = ldsi(sb + SM_AJ + (r0loc + 8) * 4);

    // pack FF A-fragments from fp32 scratch (feat cols 0..31, 2 ksteps)
    {
        u32 scr = sb + SM_EF;
        u32 ffW = sb + SM_FF + (u32)warp * 1024u;
#pragma unroll
        for (int ks = 0; ks < 2; ks++){
            u32 base = scr + ((u32)r0loc * FSTR + (u32)(ks * 16 + 2 * t)) * 4u;
            float2 q0 = ldsf2(base);
            float2 q1 = ldsf2(base + 8u * FSTR * 4u);
            float2 q2 = ldsf2(base + 32u);
            float2 q3 = ldsf2(base + 8u * FSTR * 4u + 32u);
            sts128(ffW + (u32)ks * 512u + (u32)lane * 16u,
                   f16x2(q0.y, q0.x), f16x2(q1.y, q1.x),
                   f16x2(q2.y, q2.x), f16x2(q3.y, q3.x));
        }
    }
    __syncthreads();   // scratch dead everywhere before EF-frag writes

    const u32 aFF = sb + SM_FF + (u32)warp * 1024u + (u32)lane * 16u;
    const u32 aEF = sb + SM_EF + (u32)warp * 4096u + (u32)lane * 16u;
    const u32 aHH = sb + SM_HH + (u32)warp * 2048u + (u32)lane * 16u;

    float acc[8][4];

    // ========== G0: ef = feat @ Wf + P0[ai] + P1[aj] + b_init ================
#pragma unroll
    for (int p = 0; p < 2; p++){
        zeroN<8>(acc);
        gemmA<2, 4>(acc, aFF, gW4 + OFF4_WF, 8, p * 4, 0, lane);
#pragma unroll
        for (int nt = 0; nt < 8; nt++){
            int c = p * 64 + nt * 8 + 2 * t;
            float2 bb  = *(const float2*)(b_init + c);
            float2 q00 = *(const float2*)(gP0 + ti0 * 128 + c);
            float2 q10 = *(const float2*)(gP1 + tj0 * 128 + c);
            float2 q01 = *(const float2*)(gP0 + ti1 * 128 + c);
            float2 q11 = *(const float2*)(gP1 + tj1 * 128 + c);
            float d0 = acc[nt][0] + bb.x + q00.x + q10.x;
            float d1 = acc[nt][1] + bb.y + q00.y + q10.y;
            float d2 = acc[nt][2] + bb.x + q01.x + q11.x;
            float d3 = acc[nt][3] + bb.y + q01.y + q11.y;
            int idx = p * 8 + nt;
            sts64(aEF + (u32)(idx >> 1) * 512u + (u32)(idx & 1) * 8u,
                  f16x2(d1, d0), f16x2(d3, d2));
        }
    }

    float mu0 = 0.f, rs0 = 0.f, mu1 = 0.f, rs1 = 0.f;

    // ========== layers =======================================================
#pragma unroll 1
    for (int l = 0; l < 3; l++){
        // --- G1: h = silu(ef@W1a + rbf@W1b + R0[ai] + R1[aj] + b1) ---
        {
            const uint4* B = gW4 + OFF4_W1(l);
            zeroN<8>(acc);
            gemmA<8, 4>(acc, aEF, B, 4, 0, 0, lane);
            gemmA<1, 4>(acc, aFF, B, 4, 0, 8, lane);   // rbf tail (rows 136+ zero)
            const float* B1 = b1 + l * 64;
            const float* R0b = gR + (l * 2    ) * 6400;
            const float* R1b = gR + (l * 2 + 1) * 6400;
#pragma unroll
            for (int nt = 0; nt < 8; nt++){
                int c = nt * 8 + 2 * t;
                float2 bb  = *(const float2*)(B1 + c);
                float2 x00 = *(const float2*)(R0b + ti0 * 64 + c);
                float2 x10 = *(const float2*)(R1b + tj0 * 64 + c);
                float2 x01 = *(const float2*)(R0b + ti1 * 64 + c);
                float2 x11 = *(const float2*)(R1b + tj1 * 64 + c);
                float d0 = silu_f(acc[nt][0] + bb.x + x00.x + x10.x);
                float d1 = silu_f(acc[nt][1] + bb.y + x00.y + x10.y);
                float d2 = silu_f(acc[nt][2] + bb.x + x01.x + x11.x);
                float d3 = silu_f(acc[nt][3] + bb.y + x01.y + x11.y);
                sts64(aHH + (u32)(nt >> 1) * 512u + (u32)(nt & 1) * 8u,
                      f16x2(d1, d0), f16x2(d3, d2));
            }
        }

        // --- G2: h = silu(h @ w2 + b2)  (thread-local slots: in-place safe) ---
        {
            zeroN<8>(acc);
            gemmA<4, 4>(acc, aHH, gW4 + OFF4_W2(l), 4, 0, 0, lane);
            const float* B2 = b2 + l * 64;
#pragma unroll
            for (int nt = 0; nt < 8; nt++){
                int c = nt * 8 + 2 * t;
                float2 bb = *(const float2*)(B2 + c);
                sts64(aHH + (u32)(nt >> 1) * 512u + (u32)(nt & 1) * 8u,
                      f16x2(silu_f(acc[nt][1] + bb.y), silu_f(acc[nt][0] + bb.x)),
                      f16x2(silu_f(acc[nt][3] + bb.y), silu_f(acc[nt][2] + bb.x)));
            }
        }

        // --- G3: ef += h @ w3 + b3 ; LN stats ---
        {
            float s10 = 0.f, s20 = 0.f, s11 = 0.f, s21 = 0.f;
            const float* B3 = b3 + l * 128;
#pragma unroll
            for (int p = 0; p < 2; p++){
                zeroN<8>(acc);
                gemmA<4, 4>(acc, aHH, gW4 + OFF4_W3(l), 8, p * 4, 0, lane);
#pragma unroll
                for (int nt = 0; nt < 8; nt++){
                    int c = p * 64 + nt * 8 + 2 * t;
                    float2 bb = *(const float2*)(B3 + c);
                    int idx = p * 8 + nt;
                    u32 ea = aEF + (u32)(idx >> 1) * 512u + (u32)(idx & 1) * 8u;
                    uint2 old = lds64(ea);
                    float2 flo = h2f(old.x);
                    float2 fhi = h2f(old.y);
                    float v0 = flo.x + acc[nt][0] + bb.x;
                    float v1 = flo.y + acc[nt][1] + bb.y;
                    float v2 = fhi.x + acc[nt][2] + bb.x;
                    float v3 = fhi.y + acc[nt][3] + bb.y;
                    s10 += v0 + v1; s20 += v0 * v0 + v1 * v1;   // row g
                    s11 += v2 + v3; s21 += v2 * v2 + v3 * v3;   // row g+8
                    sts64(ea, f16x2(v1, v0), f16x2(v3, v2));
                }
            }
            const u32 m = 0xffffffffu;
            s10 += __shfl_xor_sync(m, s10, 1); s10 += __shfl_xor_sync(m, s10, 2);
            s20 += __shfl_xor_sync(m, s20, 1); s20 += __shfl_xor_sync(m, s20, 2);
            s11 += __shfl_xor_sync(m, s11, 1); s11 += __shfl_xor_sync(m, s11, 2);
            s21 += __shfl_xor_sync(m, s21, 1); s21 += __shfl_xor_sync(m, s21, 2);
            mu0 = s10 * 0.0078125f;
            rs0 = rsqrtf(s20 * 0.0078125f - mu0 * mu0 + 1e-5f);
            mu1 = s11 * 0.0078125f;
            rs1 = rsqrtf(s21 * 0.0078125f - mu1 * mu1 + 1e-5f);
        }

        // --- G4: t1 = silu(sh @ tpw1 + tpb1)  (tpw1 k-shifted at pack time) ---
        {
            zeroN<8>(acc);
            gemmA<2, 4>(acc, aFF, gW4 + OFF4_TP1(l), 4, 0, 0, lane);
            const float* TB = tpb1 + l * 64;
#pragma unroll
            for (int nt = 0; nt < 8; nt++){
                int c = nt * 8 + 2 * t;
                float2 bb = *(const float2*)(TB + c);
                sts64(aHH + (u32)(nt >> 1) * 512u + (u32)(nt & 1) * 8u,
                      f16x2(silu_f(acc[nt][1] + bb.y), silu_f(acc[nt][0] + bb.x)),
                      f16x2(silu_f(acc[nt][3] + bb.y), silu_f(acc[nt][2] + bb.x)));
            }
        }

        // --- G5: w = t1 @ tpw2 + tpb2 ; ef = LN(ef) * w ---
        {
            const float* TB = tpb2 + l * 128;
            const float* LG = ln_g + l * 128;
            const float* LB = ln_b + l * 128;
#pragma unroll
            for (int p = 0; p < 2; p++){
                zeroN<8>(acc);
                gemmA<4, 4>(acc, aHH, gW4 + OFF4_TP2(l), 8, p * 4, 0, lane);
#pragma unroll
                for (int nt = 0; nt < 8; nt++){
                    int c = p * 64 + nt * 8 + 2 * t;
                    float2 bb = *(const float2*)(TB + c);
                    float2 lg = *(const float2*)(LG + c);
                    float2 lb = *(const float2*)(LB + c);
                    int idx = p * 8 + nt;
                    u32 ea = aEF + (u32)(idx >> 1) * 512u + (u32)(idx & 1) * 8u;
                    uint2 old = lds64(ea);
                    float2 flo = h2f(old.x);
                    float2 fhi = h2f(old.y);
                    float v0 = ((flo.x - mu0) * rs0 * lg.x + lb.x) * (acc[nt][0] + bb.x);
                    float v1 = ((flo.y - mu0) * rs0 * lg.y + lb.y) * (acc[nt][1] + bb.y);
                    float v2 = ((fhi.x - mu1) * rs1 * lg.x + lb.x) * (acc[nt][2] + bb.x);
                    float v3 = ((fhi.y - mu1) * rs1 * lg.y + lb.y) * (acc[nt][3] + bb.y);
                    sts64(ea, f16x2(v1, v0), f16x2(v3, v2));
                }
            }
        }
        __syncthreads();   // keep warps phase-coherent for L1 reuse of gW4
    }

    // ========== head =========================================================
    // G6: h = silu(ef @ hw1 + hb1)
    {
        zeroN<8>(acc);
        gemmA<8, 4>(acc, aEF, gW4 + OFF4_HW1, 4, 0, 0, lane);
#pragma unroll
        for (int nt = 0; nt < 8; nt++){
            int c = nt * 8 + 2 * t;
            float2 bb = *(const float2*)(hb1 + c);
            sts64(aHH + (u32)(nt >> 1) * 512u + (u32)(nt & 1) * 8u,
                  f16x2(silu_f(acc[nt][1] + bb.y), silu_f(acc[nt][0] + bb.x)),
                  f16x2(silu_f(acc[nt][3] + bb.y), silu_f(acc[nt][2] + bb.x)));
        }
    }

    // G7: q = silu(h @ hw2 + hb2); pe = q . hw3   (hb3 folded in finalize)
    double pes = 0.0;
    {
        float acc4[4][4];
        zeroN<4>(acc4);
        gemmA<4, 2>(acc4, aHH, gW4 + OFF4_HW2, 2, 0, 0, lane);
        float pe0 = 0.f, pe1 = 0.f;
#pragma unroll
        for (int nt = 0; nt < 4; nt++){
            int c = nt * 8 + 2 * t;
            float2 bb = *(const float2*)(hb2 + c);
            float2 ww = *(const float2*)(hw3 + c);
            pe0 += silu_f(acc4[nt][0] + bb.x) * ww.x + silu_f(acc4[nt][1] + bb.y) * ww.y;
            pe1 += silu_f(acc4[nt][2] + bb.x) * ww.x + silu_f(acc4[nt][3] + bb.y) * ww.y;
        }
        const u32 m = 0xffffffffu;
        pe0 += __shfl_xor_sync(m, pe0, 1); pe0 += __shfl_xor_sync(m, pe0, 2);
        pe1 += __shfl_xor_sync(m, pe1, 1); pe1 += __shfl_xor_sync(m, pe1, 2);
        if (t == 0){
            int e0 = blockIdx.x * EPC + r0loc;
            if (e0 < E)     pes += (double)pe0;
            if (e0 + 8 < E) pes += (double)pe1;
        }
    }

    // ---------------- per-block deterministic reduction ----------------------
    __syncthreads();                       // FF region free -> reuse as double[]
    double* red = (double*)(smem);
    red[tid] = pes;
    __syncthreads();
    if (tid < 112) red[tid] += red[tid + 112];
    __syncthreads();
    if (tid <  56) red[tid] += red[tid +  56];
    __syncthreads();
    if (tid <  28) red[tid] += red[tid +  28];
    __syncthreads();
    if (tid <  14) red[tid] += red[tid +  14];
    __syncthreads();
    if (tid == 0){
        double s = 0.0;
#pragma unroll
        for (int i = 0; i < 14; i++) s += red[i];
        g_partial[blockIdx.x] = s;
    }
}

// ---------------------------------------------------------------------------
// prep: fold node_emb through w_init / w1 per atom type (fp32 exact)
__global__ void prep_kernel(const float* __restrict__ node_emb,
                            const float* __restrict__ w_init,
                            const float* __restrict__ w1)
{
    __shared__ float emb[64];
    int tpe = blockIdx.x;
    if (threadIdx.x < 64) emb[threadIdx.x] = node_emb[tpe * 64 + threadIdx.x];
    __syncthreads();
    int c = threadIdx.x;
    if (c < 128){
        float s0 = 0.0f, s1 = 0.0f;
#pragma unroll 4
        for (int k = 0; k < 64; k++){
            float e = emb[k];
            s0 += e * __ldg(w_init + k * 128 + c);
            s1 += e * __ldg(w_init + (64 + k) * 128 + c);
        }
        gP0[tpe * 128 + c] = s0;
        gP1[tpe * 128 + c] = s1;
    }
    if (c < 64){
#pragma unroll 1
        for (int ls = 0; ls < 6; ls++){
            int l = ls >> 1, s = ls & 1;
            const float* W = w1 + l * 264 * 64 + (128 + s * 64) * 64;
            float r = 0.0f;
#pragma unroll 4
            for (int k = 0; k < 64; k++) r += emb[k] * __ldg(W + k * 64 + c);
            gR[(ls * 100 + tpe) * 64 + c] = r;
        }
    }
}

// ---------------------------------------------------------------------------
__global__ void final_kernel(const int *__restrict__ an,
                             const float *__restrict__ atomic_e,
                             const float *__restrict__ hb3,
                             float *__restrict__ out, int N, int nB, int E) {
    __shared__ double red[256];
    double s = 0.0;
    for (int i = threadIdx.x; i < nB; i += 256) s += g_partial[i];
    for (int i = threadIdx.x; i < N; i += 256)
        s += (double)__ldg(atomic_e + __ldg(an + i));
    if (threadIdx.x == 0) s += (double)E * (double)__ldg(hb3);
    red[threadIdx.x] = s;
    __syncthreads();
    for (int off = 128; off > 0; off >>= 1) {
        if (threadIdx.x < off) red[threadIdx.x] += red[threadIdx.x + off];
        __syncthreads();
    }
    if (threadIdx.x == 0) out[0] = (float)red[0];
}

// ---------------------------------------------------------------------------
extern "C" void kernel_launch(void *const *d_in, const int *in_sizes, int n_in,
                              void *d_out, int out_size) {
    (void)n_in; (void)out_size;
    const int   *an    = (const int *)d_in[0];
    const float *pos   = (const float *)d_in[1];
    const int   *eidx  = (const int *)d_in[2];
    const float *nemb  = (const float *)d_in[3];
    const float *ae    = (const float *)d_in[4];
    const float *w_init= (const float *)d_in[5];
    const float *b_init= (const float *)d_in[6];
    const float *w1    = (const float *)d_in[7];
    const float *b1    = (const float *)d_in[8];
    const float *w2    = (const float *)d_in[9];
    const float *b2    = (const float *)d_in[10];
    const float *w3    = (const float *)d_in[11];
    const float *b3    = (const float *)d_in[12];
    const float *lng   = (const float *)d_in[13];
    const float *lnb   = (const float *)d_in[14];
    const float *tpw1  = (const float *)d_in[15];
    const float *tpb1  = (const float *)d_in[16];
    const float *tpw2  = (const float *)d_in[17];
    const float *tpb2  = (const float *)d_in[18];
    const float *hw1   = (const float *)d_in[19];
    const float *hb1   = (const float *)d_in[20];
    const float *hw2   = (const float *)d_in[21];
    const float *hb2   = (const float *)d_in[22];
    const float *hw3   = (const float *)d_in[23];
    const float *hb3   = (const float *)d_in[24];

    const int N = in_sizes[0];
    const int E = in_sizes[2] / 2;
    int nB = (E + EPC - 1) / EPC;
    if (nB > 8192) nB = 8192;   // g_partial guard (800k edges -> 7143 blocks)

    cudaFuncSetAttribute(edge_kernel,
                         cudaFuncAttributeMaxDynamicSharedMemorySize, SM_TOTAL);

    round_kernel<<<(1568 + 127) / 128, 128>>>(w_init, w1, w2, w3,
                                              tpw1, tpw2, hw1, hw2);
    pack_frag_kernel<<<(PACK4_TOT + 255) / 256, 256>>>();
    prep_kernel<<<100, 128>>>(nemb, w_init, w1);
    edge_kernel<<<nB, TPB, SM_TOTAL>>>(
        an, pos, eidx, b_init, b1, b2, b3,
        lng, lnb, tpb1, tpb2, hb1, hb2, hw3, E);
    final_kernel<<<1, 256>>>(an, ae, hb3, (float *)d_out, N, nB, E);
}

// round 15
// speedup vs baseline: 1.1508x; 1.0470x over previous
#include <cuda_runtime.h>
#include <cuda_fp16.h>

typedef unsigned int u32;

#define TPB 224
#define EPC 112            // edges per CTA (7 warps x 16 rows)
#define FSTR 34            // fp32 feat scratch row stride (words)

#define SM_FF 0            // feat A-frags: 7w * 2ks * 512B = 7168
#define SM_EF 7168         // ef A-frags: 7w * 8ks * 512B = 28672 (+scratch alias)
#define SM_HH 35840        // h  A-frags: 7w * 4ks * 512B = 14336
#define SM_AI 50176        // 112 * 4
#define SM_AJ 50624
#define SM_TOTAL 51072

// ---- prepacked f16 weight image, uint4 = two n-adjacent B fragments ---------
#define PACK_TOT  27392
#define PACK4_TOT 13696
#define OFF4_WF      0
#define OFF4_W1(l)   (512   + (l) * 1152)
#define OFF4_W2(l)   (3968  + (l) * 512)
#define OFF4_W3(l)   (5504  + (l) * 1024)
#define OFF4_TP1(l)  (8576  + (l) * 256)
#define OFF4_TP2(l)  (9344  + (l) * 1024)
#define OFF4_HW1     12416
#define OFF4_HW2     13440

__device__ uint4  gW4[PACK4_TOT];
__device__ unsigned short gH[4 * PACK_TOT];   // canonical [seg][k][n] f16 image
__device__ double g_partial[8192];
__device__ float  gP0[100 * 128];
__device__ float  gP1[100 * 128];
__device__ float  gR [3 * 2 * 100 * 64];
// permuted-f16 gather tables: entry [type][q][t] = 4 f16 (cols 16q+2t,+1,+8,+9)
__device__ uint2  gP0h[100 * 8 * 4];
__device__ uint2  gP1h[100 * 8 * 4];
__device__ uint2  gRh [6 * 100 * 4 * 4];

__constant__ int c_soff[19] = {0, 1024, 3328, 5632, 7936, 8960, 9984,
                               11008, 13056, 15104, 17152, 17664, 18176,
                               18688, 20736, 22784, 24832, 26880, 27392};
__constant__ int c_soff4[19] = {0, 512, 1664, 2816, 3968, 4480, 4992,
                                5504, 6528, 7552, 8576, 8832, 9088,
                                9344, 10368, 11392, 12416, 13440, 13696};
__constant__ int c_ntg [18] = {16, 8,8,8, 8,8,8, 16,16,16, 8,8,8, 16,16,16, 8, 4};
__constant__ int c_n   [18] = {128, 64,64,64, 64,64,64, 128,128,128,
                               64,64,64, 128,128,128, 64, 32};
__constant__ int c_kreal[18]= {17, 136,136,136, 64,64,64, 64,64,64,
                               17,17,17, 64,64,64, 128, 64};
__constant__ int c_remap[18]= {0, 1,1,1, 0,0,0, 0,0,0, 2,2,2, 0,0,0, 0, 0};
__constant__ int c_src [18] = {0, 1,1,1, 2,2,2, 3,3,3, 4,4,4, 5,5,5, 6, 7};
__constant__ int c_woff[18] = {16384, 0,16896,33792, 0,4096,8192, 0,8192,16384,
                               0,576,1152, 0,8192,16384, 0, 0};
__constant__ int c_ncol[19] = {0, 128, 192, 256, 320, 384, 448, 512,
                               640, 768, 896, 960, 1024, 1088,
                               1216, 1344, 1472, 1536, 1568};

// ---------------- low-level helpers -----------------------------------------
__device__ __forceinline__ u32 smem_u32(const void* p){
    u32 a;
    asm("{ .reg .u64 t; cvta.to.shared.u64 t, %1; cvt.u32.u64 %0, t; }"
        : "=r"(a) : "l"(p));
    return a;
}
__device__ __forceinline__ float silu_f(float x){ return x / (1.0f + __expf(-x)); }
__device__ __forceinline__ int ldsi(u32 a){
    int v; asm volatile("ld.shared.b32 %0, [%1];" : "=r"(v) : "r"(a)); return v;
}
__device__ __forceinline__ void stsf(u32 a, float v){
    asm volatile("st.shared.f32 [%0], %1;" :: "r"(a), "f"(v));
}
__device__ __forceinline__ void stsi(u32 a, int v){
    asm volatile("st.shared.b32 [%0], %1;" :: "r"(a), "r"(v));
}
__device__ __forceinline__ float2 ldsf2(u32 a){
    float2 v; asm volatile("ld.shared.v2.f32 {%0,%1}, [%2];"
                           : "=f"(v.x), "=f"(v.y) : "r"(a));
    return v;
}
__device__ __forceinline__ uint4 lds128(u32 a){
    uint4 v; asm volatile("ld.shared.v4.u32 {%0,%1,%2,%3}, [%4];"
        : "=r"(v.x), "=r"(v.y), "=r"(v.z), "=r"(v.w) : "r"(a));
    return v;
}
__device__ __forceinline__ uint2 lds64(u32 a){
    uint2 v; asm volatile("ld.shared.v2.u32 {%0,%1}, [%2];"
        : "=r"(v.x), "=r"(v.y) : "r"(a));
    return v;
}
__device__ __forceinline__ void sts64(u32 a, u32 x, u32 y){
    asm volatile("st.shared.v2.u32 [%0], {%1,%2};" :: "r"(a), "r"(x), "r"(y));
}
__device__ __forceinline__ void sts128(u32 a, u32 x, u32 y, u32 z, u32 w){
    asm volatile("st.shared.v4.u32 [%0], {%1,%2,%3,%4};"
                 :: "r"(a), "r"(x), "r"(y), "r"(z), "r"(w));
}
// pack two f32 -> f16x2 (first src lands in HIGH half)
__device__ __forceinline__ u32 f16x2(float hi, float lo){
    u32 r; asm("cvt.rn.f16x2.f32 %0, %1, %2;" : "=r"(r) : "f"(hi), "f"(lo));
    return r;
}
__device__ __forceinline__ float2 h2f(u32 v){
    float2 f;
    asm("{.reg .f16 l, h; mov.b32 {l, h}, %2; cvt.f32.f16 %0, l; cvt.f32.f16 %1, h;}"
        : "=f"(f.x), "=f"(f.y) : "r"(v));
    return f;
}
__device__ __forceinline__ void mma_f16(float* d, const u32* a, u32 b0, u32 b1){
    asm volatile("mma.sync.aligned.m16n8k16.row.col.f32.f16.f16.f32 "
        "{%0,%1,%2,%3}, {%4,%5,%6,%7}, {%8,%9}, {%0,%1,%2,%3};"
        : "+f"(d[0]), "+f"(d[1]), "+f"(d[2]), "+f"(d[3])
        : "r"(a[0]), "r"(a[1]), "r"(a[2]), "r"(a[3]), "r"(b0), "r"(b1));
}

template<int NT>
__device__ __forceinline__ void zeroN(float (*a)[4]){
#pragma unroll
    for (int i = 0; i < NT; i++)
#pragma unroll
        for (int j = 0; j < 4; j++) a[i][j] = 0.0f;
}

// ---- warp GEMM (M=16): A frag slots in smem (512B/kstep), B uint4 pairs -----
template<int NKS, int NTP>
__device__ __forceinline__ void gemmA(float (*acc)[4], u32 aSlots,
                                      const uint4* __restrict__ B,
                                      int NTGP, int ntgp0, int ksB0, int lane){
#pragma unroll
    for (int s = 0; s < NKS; s++){
        uint4 av = lds128(aSlots + (u32)s * 512u);
        u32 a[4] = {av.x, av.y, av.z, av.w};
        const uint4* bp = B + ((u32)(ksB0 + s) * NTGP + ntgp0) * 32 + lane;
#pragma unroll
        for (int p = 0; p < NTP; p++){
            uint4 b = __ldg(bp + p * 32);
            mma_f16(acc[2 * p],     a, b.x, b.y);
            mma_f16(acc[2 * p + 1], a, b.z, b.w);
        }
    }
}

// ---------------------------------------------------------------------------
// round_kernel: cascade (error-feedback) rounding of each weight column to f16.
__global__ void round_kernel(const float* __restrict__ w_init,
                             const float* __restrict__ w1,
                             const float* __restrict__ w2,
                             const float* __restrict__ w3,
                             const float* __restrict__ tpw1,
                             const float* __restrict__ tpw2,
                             const float* __restrict__ hw1,
                             const float* __restrict__ hw2)
{
    int col = blockIdx.x * blockDim.x + threadIdx.x;
    if (col >= 1568) return;
    int s = 0;
    while (s + 1 < 18 && col >= c_ncol[s + 1]) s++;
    int n = col - c_ncol[s];
    const float* srcs[8] = {w_init, w1, w2, w3, tpw1, tpw2, hw1, hw2};
    const float* W = srcs[c_src[s]] + c_woff[s];
    int N = c_n[s], Kreal = c_kreal[s], remap = c_remap[s];
    int Kpad = 16 * ((c_soff[s + 1] - c_soff[s]) / (c_ntg[s] * 32));
    unsigned short* out = gH + 4 * c_soff[s];
    float e = 0.0f;
    for (int k = 0; k < Kpad; k++){
        int r = k;
        bool real = true;
        if (remap == 1){
            if (k < 128)      r = k;
            else if (k < 136) r = k + 128;
            else              real = false;
        } else if (remap == 2){           // tpw1: shifted by +8 (sh at cols 8..16)
            if (k >= 8 && k < 17) r = k - 8; else real = false;
        } else {
            if (k >= Kreal) real = false;
        }
        unsigned short q = 0;
        if (real){
            float tt = __ldg(W + r * N + n) + e;
            __half h = __float2half_rn(tt);
            e = tt - __half2float(h);
            q = __half_as_ushort(h);
        }
        out[k * N + n] = q;
    }
}

// pack_frag: gather rounded f16 into uint4 image (two n-adjacent fragments).
__global__ void pack_frag_kernel()
{
    int i = blockIdx.x * blockDim.x + threadIdx.x;
    if (i >= PACK4_TOT) return;
    int s = 0;
    while (s + 1 < 18 && i >= c_soff4[s + 1]) s++;
    int local = i - c_soff4[s];
    int lane = local & 31, rest = local >> 5;
    int NTGP = c_ntg[s] >> 1;
    int ntgp = rest % NTGP, ks = rest / NTGP;
    int t = lane & 3, g = lane >> 2;
    int N = c_n[s];
    const unsigned short* src = gH + 4 * c_soff[s];
    int k0 = ks * 16 + 2 * t;
    int n0 = (2 * ntgp) * 8 + g;
    int n1 = n0 + 8;
    u32 a0 = src[(k0    ) * N + n0], a1 = src[(k0 + 1) * N + n0];
    u32 a8 = src[(k0 + 8) * N + n0], a9 = src[(k0 + 9) * N + n0];
    u32 b0 = src[(k0    ) * N + n1], b1 = src[(k0 + 1) * N + n1];
    u32 b8 = src[(k0 + 8) * N + n1], b9 = src[(k0 + 9) * N + n1];
    uint4 o;
    o.x = a0 | (a1 << 16);
    o.y = a8 | (a9 << 16);
    o.z = b0 | (b1 << 16);
    o.w = b8 | (b9 << 16);
    gW4[i] = o;
}

// repack P/R tables into fragment-gather-ordered f16 uint2 entries
__global__ void repack_kernel()
{
    int i = blockIdx.x * blockDim.x + threadIdx.x;
    if (i < 6400){                         // P tables: 2 x 100 x 8q x 4t / 2tb
        int t = i & 3, rest = i >> 2;
        int q = rest & 7; rest >>= 3;
        int type = rest % 100, tb = rest / 100;
        const float* src = (tb ? gP1 : gP0) + type * 128 + q * 16 + 2 * t;
        uint2 o;
        o.x = f16x2(src[1], src[0]);
        o.y = f16x2(src[9], src[8]);
        (tb ? gP1h : gP0h)[(type * 8 + q) * 4 + t] = o;
    } else if (i < 16000){                 // R tables: 6 x 100 x 4q x 4t
        int j = i - 6400;
        int t = j & 3, rest = j >> 2;
        int q = rest & 3; rest >>= 2;
        int type = rest % 100, ls = rest / 100;
        const float* src = gR + (ls * 100 + type) * 64 + q * 16 + 2 * t;
        uint2 o;
        o.x = f16x2(src[1], src[0]);
        o.y = f16x2(src[9], src[8]);
        gRh[((ls * 100 + type) * 4 + q) * 4 + t] = o;
    }
}

// ---------------------------------------------------------------------------
__global__ __launch_bounds__(TPB, 4) void edge_kernel(
    const int *__restrict__ an, const float *__restrict__ pos,
    const int *__restrict__ eidx,
    const float *__restrict__ b_init,
    const float *__restrict__ b1, const float *__restrict__ b2,
    const float *__restrict__ b3,
    const float *__restrict__ ln_g, const float *__restrict__ ln_b,
    const float *__restrict__ tpb1, const float *__restrict__ tpb2,
    const float *__restrict__ hb1, const float *__restrict__ hb2,
    const float *__restrict__ hw3,
    int E)
{
    extern __shared__ char smem[];
    const u32 sb  = smem_u32(smem);
    const int tid = threadIdx.x;
    const int warp = tid >> 5, lane = tid & 31;
    const int g = lane >> 2, t = lane & 3;
    const int woff16 = warp * 16;

    // ---------------- per-edge features (threads 0..111) into fp32 scratch ---
    if (tid < EPC){
        int e = blockIdx.x * EPC + tid;
        if (e >= E) e = E - 1;
        const int rowi = eidx[e];
        const int coli = eidx[E + e];
        const float vx = pos[3 * coli + 0] - pos[3 * rowi + 0];
        const float vy = pos[3 * coli + 1] - pos[3 * rowi + 1];
        const float vz = pos[3 * coli + 2] - pos[3 * rowi + 2];
        const float d = sqrtf(vx * vx + vy * vy + vz * vz);

        u32 r0 = sb + SM_EF + (u32)tid * (FSTR * 4);   // scratch aliases EF
        float env = (d < 5.0f) ? (0.5f * (cosf(d * 0.6283185307179586f) + 1.0f)) : 0.0f;
        const float cen[8] = { 0.98078528040323044f,  0.83146961230254524f,
                               0.55557023301960218f,  0.19509032201612825f,
                              -0.19509032201612825f, -0.55557023301960218f,
                              -0.83146961230254524f, -0.98078528040323044f};
#pragma unroll
        for (int i = 0; i < 8; i++){
            float z = (d - cen[i] * 5.0f) * 1.6f;
            stsf(r0 + i * 4, __expf(-0.5f * z * z) * env);
        }
        float r = fmaxf(d, 1e-8f);
        float inv = 1.0f / r;
        float ux = vx * inv, uy = vy * inv, uz = vz * inv;
        stsf(r0 +  8 * 4, 0.28209479177387814f);
        stsf(r0 +  9 * 4, -0.4886025119029199f * uy);
        stsf(r0 + 10 * 4,  0.4886025119029199f * uz);
        stsf(r0 + 11 * 4, -0.4886025119029199f * ux);
        stsf(r0 + 12 * 4,  1.0925484305920792f * ux * uy);
        stsf(r0 + 13 * 4, -1.0925484305920792f * uy * uz);
        stsf(r0 + 14 * 4,  0.94617469575756f * uz * uz
                          - 0.31539156525252f * (ux * ux + uy * uy));
        stsf(r0 + 15 * 4, -1.0925484305920792f * ux * uz);
        stsf(r0 + 16 * 4,  0.5462742152960396f * (ux * ux - uy * uy));
#pragma unroll
        for (int i = 17; i < 32; i++) stsf(r0 + i * 4, 0.0f);
        stsi(sb + SM_AI + tid * 4, an[rowi]);
        stsi(sb + SM_AJ + tid * 4, an[coli]);
    }
    __syncthreads();

    const int r0loc = woff16 + g;
    const int ti0 = ldsi(sb + SM_AI + r0loc * 4);
    const int tj0 = ldsi(sb + SM_AJ + r0loc * 4);
    const int ti1 = ldsi(sb + SM_AI + (r0loc + 8) * 4);
    const int tj1 = ldsi(sb + SM_AJ + (r0loc + 8) * 4);

    // pack FF A-fragments from fp32 scratch (feat cols 0..31, 2 ksteps)
    {
        u32 scr = sb + SM_EF;
        u32 ffW = sb + SM_FF + (u32)warp * 1024u;
#pragma unroll
        for (int ks = 0; ks < 2; ks++){
            u32 base = scr + ((u32)r0loc * FSTR + (u32)(ks * 16 + 2 * t)) * 4u;
            float2 q0 = ldsf2(base);
            float2 q1 = ldsf2(base + 8u * FSTR * 4u);
            float2 q2 = ldsf2(base + 32u);
            float2 q3 = ldsf2(base + 8u * FSTR * 4u + 32u);
            sts128(ffW + (u32)ks * 512u + (u32)lane * 16u,
                   f16x2(q0.y, q0.x), f16x2(q1.y, q1.x),
                   f16x2(q2.y, q2.x), f16x2(q3.y, q3.x));
        }
    }
    __syncthreads();   // scratch dead everywhere before EF-frag writes

    const u32 aFF = sb + SM_FF + (u32)warp * 1024u + (u32)lane * 16u;
    const u32 aEF = sb + SM_EF + (u32)warp * 4096u + (u32)lane * 16u;
    const u32 aHH = sb + SM_HH + (u32)warp * 2048u + (u32)lane * 16u;

    float acc[8][4];

    // ========== G0: ef = feat @ Wf + P0[ai] + P1[aj] + b_init ================
#pragma unroll
    for (int p = 0; p < 2; p++){
        zeroN<8>(acc);
        gemmA<2, 4>(acc, aFF, gW4 + OFF4_WF, 8, p * 4, 0, lane);
#pragma unroll
        for (int ntp = 0; ntp < 4; ntp++){
            int q = p * 4 + ntp;
            uint2 A00 = __ldg(gP0h + (ti0 * 8 + q) * 4 + t);
            uint2 A10 = __ldg(gP1h + (tj0 * 8 + q) * 4 + t);
            uint2 A01 = __ldg(gP0h + (ti1 * 8 + q) * 4 + t);
            uint2 A11 = __ldg(gP1h + (tj1 * 8 + q) * 4 + t);
#pragma unroll
            for (int e2 = 0; e2 < 2; e2++){
                int nt = 2 * ntp + e2;
                int c = p * 64 + nt * 8 + 2 * t;
                float2 bb  = *(const float2*)(b_init + c);
                float2 q00 = h2f(e2 ? A00.y : A00.x);
                float2 q10 = h2f(e2 ? A10.y : A10.x);
                float2 q01 = h2f(e2 ? A01.y : A01.x);
                float2 q11 = h2f(e2 ? A11.y : A11.x);
                float d0 = acc[nt][0] + bb.x + q00.x + q10.x;
                float d1 = acc[nt][1] + bb.y + q00.y + q10.y;
                float d2 = acc[nt][2] + bb.x + q01.x + q11.x;
                float d3 = acc[nt][3] + bb.y + q01.y + q11.y;
                int idx = p * 8 + nt;
                sts64(aEF + (u32)(idx >> 1) * 512u + (u32)(idx & 1) * 8u,
                      f16x2(d1, d0), f16x2(d3, d2));
            }
        }
    }

    float mu0 = 0.f, rs0 = 0.f, mu1 = 0.f, rs1 = 0.f;

    // ========== layers =======================================================
#pragma unroll 1
    for (int l = 0; l < 3; l++){
        // --- G1: h = silu(ef@W1a + rbf@W1b + R0[ai] + R1[aj] + b1) ---
        {
            const uint4* B = gW4 + OFF4_W1(l);
            zeroN<8>(acc);
            gemmA<8, 4>(acc, aEF, B, 4, 0, 0, lane);
            gemmA<1, 4>(acc, aFF, B, 4, 0, 8, lane);   // rbf tail (rows 136+ zero)
            const float* B1 = b1 + l * 64;
            const uint2* R0h = gRh + ((l * 2    ) * 100) * 16;
            const uint2* R1h = gRh + ((l * 2 + 1) * 100) * 16;
#pragma unroll
            for (int ntp = 0; ntp < 4; ntp++){
                uint2 X00 = __ldg(R0h + (ti0 * 4 + ntp) * 4 + t);
                uint2 X10 = __ldg(R1h + (tj0 * 4 + ntp) * 4 + t);
                uint2 X01 = __ldg(R0h + (ti1 * 4 + ntp) * 4 + t);
                uint2 X11 = __ldg(R1h + (tj1 * 4 + ntp) * 4 + t);
#pragma unroll
                for (int e2 = 0; e2 < 2; e2++){
                    int nt = 2 * ntp + e2;
                    int c = nt * 8 + 2 * t;
                    float2 bb  = *(const float2*)(B1 + c);
                    float2 x00 = h2f(e2 ? X00.y : X00.x);
                    float2 x10 = h2f(e2 ? X10.y : X10.x);
                    float2 x01 = h2f(e2 ? X01.y : X01.x);
                    float2 x11 = h2f(e2 ? X11.y : X11.x);
                    float d0 = silu_f(acc[nt][0] + bb.x + x00.x + x10.x);
                    float d1 = silu_f(acc[nt][1] + bb.y + x00.y + x10.y);
                    float d2 = silu_f(acc[nt][2] + bb.x + x01.x + x11.x);
                    float d3 = silu_f(acc[nt][3] + bb.y + x01.y + x11.y);
                    sts64(aHH + (u32)(nt >> 1) * 512u + (u32)(nt & 1) * 8u,
                          f16x2(d1, d0), f16x2(d3, d2));
                }
            }
        }

        // --- G2: h = silu(h @ w2 + b2)  (thread-local slots: in-place safe) ---
        {
            zeroN<8>(acc);
            gemmA<4, 4>(acc, aHH, gW4 + OFF4_W2(l), 4, 0, 0, lane);
            const float* B2 = b2 + l * 64;
#pragma unroll
            for (int nt = 0; nt < 8; nt++){
                int c = nt * 8 + 2 * t;
                float2 bb = *(const float2*)(B2 + c);
                sts64(aHH + (u32)(nt >> 1) * 512u + (u32)(nt & 1) * 8u,
                      f16x2(silu_f(acc[nt][1] + bb.y), silu_f(acc[nt][0] + bb.x)),
                      f16x2(silu_f(acc[nt][3] + bb.y), silu_f(acc[nt][2] + bb.x)));
            }
        }

        // --- G3: ef += h @ w3 + b3 ; LN stats ---
        {
            float s10 = 0.f, s20 = 0.f, s11 = 0.f, s21 = 0.f;
            const float* B3 = b3 + l * 128;
#pragma unroll
            for (int p = 0; p < 2; p++){
                zeroN<8>(acc);
                gemmA<4, 4>(acc, aHH, gW4 + OFF4_W3(l), 8, p * 4, 0, lane);
#pragma unroll
                for (int nt = 0; nt < 8; nt++){
                    int c = p * 64 + nt * 8 + 2 * t;
                    float2 bb = *(const float2*)(B3 + c);
                    int idx = p * 8 + nt;
                    u32 ea = aEF + (u32)(idx >> 1) * 512u + (u32)(idx & 1) * 8u;
                    uint2 old = lds64(ea);
                    float2 flo = h2f(old.x);
                    float2 fhi = h2f(old.y);
                    float v0 = flo.x + acc[nt][0] + bb.x;
                    float v1 = flo.y + acc[nt][1] + bb.y;
                    float v2 = fhi.x + acc[nt][2] + bb.x;
                    float v3 = fhi.y + acc[nt][3] + bb.y;
                    s10 += v0 + v1; s20 += v0 * v0 + v1 * v1;   // row g
                    s11 += v2 + v3; s21 += v2 * v2 + v3 * v3;   // row g+8
                    sts64(ea, f16x2(v1, v0), f16x2(v3, v2));
                }
            }
            const u32 m = 0xffffffffu;
            s10 += __shfl_xor_sync(m, s10, 1); s10 += __shfl_xor_sync(m, s10, 2);
            s20 += __shfl_xor_sync(m, s20, 1); s20 += __shfl_xor_sync(m, s20, 2);
            s11 += __shfl_xor_sync(m, s11, 1); s11 += __shfl_xor_sync(m, s11, 2);
            s21 += __shfl_xor_sync(m, s21, 1); s21 += __shfl_xor_sync(m, s21, 2);
            mu0 = s10 * 0.0078125f;
            rs0 = rsqrtf(s20 * 0.0078125f - mu0 * mu0 + 1e-5f);
            mu1 = s11 * 0.0078125f;
            rs1 = rsqrtf(s21 * 0.0078125f - mu1 * mu1 + 1e-5f);
        }

        // --- G4: t1 = silu(sh @ tpw1 + tpb1)  (tpw1 k-shifted at pack time) ---
        {
            zeroN<8>(acc);
            gemmA<2, 4>(acc, aFF, gW4 + OFF4_TP1(l), 4, 0, 0, lane);
            const float* TB = tpb1 + l * 64;
#pragma unroll
            for (int nt = 0; nt < 8; nt++){
                int c = nt * 8 + 2 * t;
                float2 bb = *(const float2*)(TB + c);
                sts64(aHH + (u32)(nt >> 1) * 512u + (u32)(nt & 1) * 8u,
                      f16x2(silu_f(acc[nt][1] + bb.y), silu_f(acc[nt][0] + bb.x)),
                      f16x2(silu_f(acc[nt][3] + bb.y), silu_f(acc[nt][2] + bb.x)));
            }
        }

        // --- G5: w = t1 @ tpw2 + tpb2 ; ef = LN(ef) * w ---
        {
            const float* TB = tpb2 + l * 128;
            const float* LG = ln_g + l * 128;
            const float* LB = ln_b + l * 128;
#pragma unroll
            for (int p = 0; p < 2; p++){
                zeroN<8>(acc);
                gemmA<4, 4>(acc, aHH, gW4 + OFF4_TP2(l), 8, p * 4, 0, lane);
#pragma unroll
                for (int nt = 0; nt < 8; nt++){
                    int c = p * 64 + nt * 8 + 2 * t;
                    float2 bb = *(const float2*)(TB + c);
                    float2 lg = *(const float2*)(LG + c);
                    float2 lb = *(const float2*)(LB + c);
                    int idx = p * 8 + nt;
                    u32 ea = aEF + (u32)(idx >> 1) * 512u + (u32)(idx & 1) * 8u;
                    uint2 old = lds64(ea);
                    float2 flo = h2f(old.x);
                    float2 fhi = h2f(old.y);
                    float v0 = ((flo.x - mu0) * rs0 * lg.x + lb.x) * (acc[nt][0] + bb.x);
                    float v1 = ((flo.y - mu0) * rs0 * lg.y + lb.y) * (acc[nt][1] + bb.y);
                    float v2 = ((fhi.x - mu1) * rs1 * lg.x + lb.x) * (acc[nt][2] + bb.x);
                    float v3 = ((fhi.y - mu1) * rs1 * lg.y + lb.y) * (acc[nt][3] + bb.y);
                    sts64(ea, f16x2(v1, v0), f16x2(v3, v2));
                }
            }
        }
        __syncthreads();   // keep warps phase-coherent for L1 reuse of gW4
    }

    // ========== head =========================================================
    // G6: h = silu(ef @ hw1 + hb1)
    {
        zeroN<8>(acc);
        gemmA<8, 4>(acc, aEF, gW4 + OFF4_HW1, 4, 0, 0, lane);
#pragma unroll
        for (int nt = 0; nt < 8; nt++){
            int c = nt * 8 + 2 * t;
            float2 bb = *(const float2*)(hb1 + c);
            sts64(aHH + (u32)(nt >> 1) * 512u + (u32)(nt & 1) * 8u,
                  f16x2(silu_f(acc[nt][1] + bb.y), silu_f(acc[nt][0] + bb.x)),
                  f16x2(silu_f(acc[nt][3] + bb.y), silu_f(acc[nt][2] + bb.x)));
        }
    }

    // G7: q = silu(h @ hw2 + hb2); pe = q . hw3   (hb3 folded in finalize)
    double pes = 0.0;
    {
        float acc4[4][4];
        zeroN<4>(acc4);
        gemmA<4, 2>(acc4, aHH, gW4 + OFF4_HW2, 2, 0, 0, lane);
        float pe0 = 0.f, pe1 = 0.f;
#pragma unroll
        for (int nt = 0; nt < 4; nt++){
            int c = nt * 8 + 2 * t;
            float2 bb = *(const float2*)(hb2 + c);
            float2 ww = *(const float2*)(hw3 + c);
            pe0 += silu_f(acc4[nt][0] + bb.x) * ww.x + silu_f(acc4[nt][1] + bb.y) * ww.y;
            pe1 += silu_f(acc4[nt][2] + bb.x) * ww.x + silu_f(acc4[nt][3] + bb.y) * ww.y;
        }
        const u32 m = 0xffffffffu;
        pe0 += __shfl_xor_sync(m, pe0, 1); pe0 += __shfl_xor_sync(m, pe0, 2);
        pe1 += __shfl_xor_sync(m, pe1, 1); pe1 += __shfl_xor_sync(m, pe1, 2);
        if (t == 0){
            int e0 = blockIdx.x * EPC + r0loc;
            if (e0 < E)     pes += (double)pe0;
            if (e0 + 8 < E) pes += (double)pe1;
        }
    }

    // ---------------- per-block deterministic reduction ----------------------
    __syncthreads();                       // FF region free -> reuse as double[]
    double* red = (double*)(smem);
    red[tid] = pes;
    __syncthreads();
    if (tid < 112) red[tid] += red[tid + 112];
    __syncthreads();
    if (tid <  56) red[tid] += red[tid +  56];
    __syncthreads();
    if (tid <  28) red[tid] += red[tid +  28];
    __syncthreads();
    if (tid <  14) red[tid] += red[tid +  14];
    __syncthreads();
    if (tid == 0){
        double s = 0.0;
#pragma unroll
        for (int i = 0; i < 14; i++) s += red[i];
        g_partial[blockIdx.x] = s;
    }
}

// ---------------------------------------------------------------------------
// prep: fold node_emb through w_init / w1 per atom type (fp32 exact)
__global__ void prep_kernel(const float* __restrict__ node_emb,
                            const float* __restrict__ w_init,
                            const float* __restrict__ w1)
{
    __shared__ float emb[64];
    int tpe = blockIdx.x;
    if (threadIdx.x < 64) emb[threadIdx.x] = node_emb[tpe * 64 + threadIdx.x];
    __syncthreads();
    int c = threadIdx.x;
    if (c < 128){
        float s0 = 0.0f, s1 = 0.0f;
#pragma unroll 4
        for (int k = 0; k < 64; k++){
            float e = emb[k];
            s0 += e * __ldg(w_init + k * 128 + c);
            s1 += e * __ldg(w_init + (64 + k) * 128 + c);
        }
        gP0[tpe * 128 + c] = s0;
        gP1[tpe * 128 + c] = s1;
    }
    if (c < 64){
#pragma unroll 1
        for (int ls = 0; ls < 6; ls++){
            int l = ls >> 1, s = ls & 1;
            const float* W = w1 + l * 264 * 64 + (128 + s * 64) * 64;
            float r = 0.0f;
#pragma unroll 4
            for (int k = 0; k < 64; k++) r += emb[k] * __ldg(W + k * 64 + c);
            gR[(ls * 100 + tpe) * 64 + c] = r;
        }
    }
}

// ---------------------------------------------------------------------------
__global__ void final_kernel(const int *__restrict__ an,
                             const float *__restrict__ atomic_e,
                             const float *__restrict__ hb3,
                             float *__restrict__ out, int N, int nB, int E) {
    __shared__ double red[256];
    double s = 0.0;
    for (int i = threadIdx.x; i < nB; i += 256) s += g_partial[i];
    for (int i = threadIdx.x; i < N; i += 256)
        s += (double)__ldg(atomic_e + __ldg(an + i));
    if (threadIdx.x == 0) s += (double)E * (double)__ldg(hb3);
    red[threadIdx.x] = s;
    __syncthreads();
    for (int off = 128; off > 0; off >>= 1) {
        if (threadIdx.x < off) red[threadIdx.x] += red[threadIdx.x + off];
        __syncthreads();
    }
    if (threadIdx.x == 0) out[0] = (float)red[0];
}

// ---------------------------------------------------------------------------
extern "C" void kernel_launch(void *const *d_in, const int *in_sizes, int n_in,
                              void *d_out, int out_size) {
    (void)n_in; (void)out_size;
    const int   *an    = (const int *)d_in[0];
    const float *pos   = (const float *)d_in[1];
    const int   *eidx  = (const int *)d_in[2];
    const float *nemb  = (const float *)d_in[3];
    const float *ae    = (const float *)d_in[4];
    const float *w_init= (const float *)d_in[5];
    const float *b_init= (const float *)d_in[6];
    const float *w1    = (const float *)d_in[7];
    const float *b1    = (const float *)d_in[8];
    const float *w2    = (const float *)d_in[9];
    const float *b2    = (const float *)d_in[10];
    const float *w3    = (const float *)d_in[11];
    const float *b3    = (const float *)d_in[12];
    const float *lng   = (const float *)d_in[13];
    const float *lnb   = (const float *)d_in[14];
    const float *tpw1  = (const float *)d_in[15];
    const float *tpb1  = (const float *)d_in[16];
    const float *tpw2  = (const float *)d_in[17];
    const float *tpb2  = (const float *)d_in[18];
    const float *hw1   = (const float *)d_in[19];
    const float *hb1   = (const float *)d_in[20];
    const float *hw2   = (const float *)d_in[21];
    const float *hb2   = (const float *)d_in[22];
    const float *hw3   = (const float *)d_in[23];
    const float *hb3   = (const float *)d_in[24];

    const int N = in_sizes[0];
    const int E = in_sizes[2] / 2;
    int nB = (E + EPC - 1) / EPC;
    if (nB > 8192) nB = 8192;   // g_partial guard (800k edges -> 7143 blocks)

    cudaFuncSetAttribute(edge_kernel,
                         cudaFuncAttributeMaxDynamicSharedMemorySize, SM_TOTAL);

    round_kernel<<<(1568 + 127) / 128, 128>>>(w_init, w1, w2, w3,
                                              tpw1, tpw2, hw1, hw2);
    pack_frag_kernel<<<(PACK4_TOT + 255) / 256, 256>>>();
    prep_kernel<<<100, 128>>>(nemb, w_init, w1);
    repack_kernel<<<(16000 + 255) / 256, 256>>>();
    edge_kernel<<<nB, TPB, SM_TOTAL>>>(
        an, pos, eidx, b_init, b1, b2, b3,
        lng, lnb, tpb1, tpb2, hb1, hb2, hw3, E);
    final_kernel<<<1, 256>>>(an, ae, hb3, (float *)d_out, N, nB, E);
}